// round 1
// baseline (speedup 1.0000x reference)
#include <cuda_runtime.h>
#include <cstdint>

// ---------------- problem constants ----------------
#define MAXN 100000
#define MAXE 1000000
#define NB   16          // graphs
#define EPT  8           // edges per thread in edge kernel

// d_small layout (floats)
#define GPE  0           // gprojE  [B*16]  (g contribution to edge core, incl be_core)
#define GPX  256         // gprojX  [B*16]  (g contribution to node core, incl bx_core)
#define NAGG 512         // node_agg [B*16]
#define EAGG 768         // edge_agg [B*16]
#define G1O  1024        // g1 [B]
#define GCO  1040        // gc [B]
#define SMALLN 1056

// ---------------- device scratch (no allocations allowed) ----------------
__device__ __align__(128) float d_ec[(size_t)MAXE * 16];    // e latent from step1
__device__ __align__(128) float d_projS[(size_t)MAXN * 16]; // x_in @ W_src
__device__ __align__(128) float d_projD[(size_t)MAXN * 16]; // x_in @ W_dst
__device__ __align__(128) float d_aggE[(size_t)MAXN * 16];  // segment sum of e_new by dst
__device__ __align__(128) float d_xc[(size_t)MAXN * 16];    // x latent from step1
__device__ __align__(128) float d_counts[MAXN];
__device__ __align__(128) float d_small[SMALLN];

// ---------------- helpers ----------------
#define RED4(p, a, b, c, d) \
    asm volatile("red.global.add.v4.f32 [%0], {%1,%2,%3,%4};" \
                 :: "l"(p), "f"(a), "f"(b), "f"(c), "f"(d) : "memory")

__device__ __forceinline__ void mac16(const float (*__restrict__ W)[16],
                                      const float* __restrict__ in,
                                      float* __restrict__ acc) {
#pragma unroll
    for (int k = 0; k < 16; k++) {
        float v = in[k];
        const float4* w = reinterpret_cast<const float4*>(&W[k][0]);
        float4 w0 = w[0], w1 = w[1], w2 = w[2], w3 = w[3];
        acc[0]  = fmaf(v, w0.x, acc[0]);  acc[1]  = fmaf(v, w0.y, acc[1]);
        acc[2]  = fmaf(v, w0.z, acc[2]);  acc[3]  = fmaf(v, w0.w, acc[3]);
        acc[4]  = fmaf(v, w1.x, acc[4]);  acc[5]  = fmaf(v, w1.y, acc[5]);
        acc[6]  = fmaf(v, w1.z, acc[6]);  acc[7]  = fmaf(v, w1.w, acc[7]);
        acc[8]  = fmaf(v, w2.x, acc[8]);  acc[9]  = fmaf(v, w2.y, acc[9]);
        acc[10] = fmaf(v, w2.z, acc[10]); acc[11] = fmaf(v, w2.w, acc[11]);
        acc[12] = fmaf(v, w3.x, acc[12]); acc[13] = fmaf(v, w3.y, acc[13]);
        acc[14] = fmaf(v, w3.z, acc[14]); acc[15] = fmaf(v, w3.w, acc[15]);
    }
}

__device__ __forceinline__ void lane_flush16(int b, const float* v, float* gbase) {
    float* p = gbase + b * 16;
    RED4(p,      v[0],  v[1],  v[2],  v[3]);
    RED4(p + 4,  v[4],  v[5],  v[6],  v[7]);
    RED4(p + 8,  v[8],  v[9],  v[10], v[11]);
    RED4(p + 12, v[12], v[13], v[14], v[15]);
}

// Warp-cooperative flush of a 16-vector keyed by graph id. Sorted index arrays
// make warps graph-uniform almost always -> butterfly reduce + 1 lane of REDs.
__device__ __forceinline__ void warp_flush16(int curB, float* v, float* gbase) {
    const unsigned full = 0xffffffffu;
    int b0 = __shfl_sync(full, curB, 0);
    bool uni = __all_sync(full, (curB == b0) || (curB < 0));
    if (uni) {
#pragma unroll
        for (int h = 0; h < 16; h++) {
            float s = v[h];
            s += __shfl_xor_sync(full, s, 16);
            s += __shfl_xor_sync(full, s, 8);
            s += __shfl_xor_sync(full, s, 4);
            s += __shfl_xor_sync(full, s, 2);
            s += __shfl_xor_sync(full, s, 1);
            v[h] = s;
        }
        if (((threadIdx.x & 31) == 0) && b0 >= 0) lane_flush16(b0, v, gbase);
    } else if (curB >= 0) {
        lane_flush16(curB, v, gbase);
    }
}

// ---------------- setup kernels ----------------
__global__ void count_kernel(const int* __restrict__ dst, int E) {
    int i = blockIdx.x * blockDim.x + threadIdx.x;
    if (i < E) atomicAdd(&d_counts[dst[i]], 1.0f);
}

// projS/projD for step1 (x_in = [x1, x1])
__global__ void __launch_bounds__(256) setup_node_kernel(
    const float* __restrict__ x,
    const float* __restrict__ Wx_enc, const float* __restrict__ bx_enc,
    const float* __restrict__ We_core, int N) {
    __shared__ __align__(16) float sWS[16][16], sWD[16][16];
    __shared__ float sWenc[16], sBenc[16];
    int t = threadIdx.x, k = t >> 4, h = t & 15;
    sWS[k][h] = We_core[(32 + k) * 16 + h] + We_core[(48 + k) * 16 + h];
    sWD[k][h] = We_core[(64 + k) * 16 + h] + We_core[(80 + k) * 16 + h];
    if (t < 16) { sWenc[t] = Wx_enc[t]; sBenc[t] = bx_enc[t]; }
    __syncthreads();
    int n = blockIdx.x * 256 + t;
    if (n >= N) return;
    float xv = x[n];
    float x1[16];
#pragma unroll
    for (int hh = 0; hh < 16; hh++) x1[hh] = fmaxf(fmaf(xv, sWenc[hh], sBenc[hh]), 0.f);
    float ps[16], pd[16];
#pragma unroll
    for (int hh = 0; hh < 16; hh++) { ps[hh] = 0.f; pd[hh] = 0.f; }
    mac16(sWS, x1, ps);
    mac16(sWD, x1, pd);
    float4* os = reinterpret_cast<float4*>(d_projS + (size_t)n * 16);
    float4* od = reinterpret_cast<float4*>(d_projD + (size_t)n * 16);
#pragma unroll
    for (int q = 0; q < 4; q++) {
        os[q] = make_float4(ps[4 * q], ps[4 * q + 1], ps[4 * q + 2], ps[4 * q + 3]);
        od[q] = make_float4(pd[4 * q], pd[4 * q + 1], pd[4 * q + 2], pd[4 * q + 3]);
    }
}

__global__ void setup_global_kernel(
    const float* __restrict__ g,
    const float* __restrict__ Wg_enc, const float* __restrict__ bg_enc,
    const float* __restrict__ We_core, const float* __restrict__ be_core,
    const float* __restrict__ Wx_core, const float* __restrict__ bx_core, int B) {
    int t = threadIdx.x;
    if (t < B) {
        float g1 = fmaxf(fmaf(g[t], Wg_enc[0], bg_enc[0]), 0.f);
        d_small[G1O + t] = g1;
        d_small[GCO + t] = g1;
    }
    __syncthreads();
    if (t < B * 16) {
        int b = t >> 4, h = t & 15;
        float g1 = d_small[G1O + b];
        d_small[GPE + t] = fmaf(g1, We_core[96 * 16 + h] + We_core[97 * 16 + h], be_core[h]);
        d_small[GPX + t] = fmaf(g1, Wx_core[48 * 16 + h] + Wx_core[49 * 16 + h], bx_core[h]);
    }
}

// ---------------- edge kernel (fused encoder + edge core + decoder + out) ----------------
template <int STEP>
__global__ void __launch_bounds__(256) edge_kernel(
    const float* __restrict__ e,
    const int* __restrict__ src, const int* __restrict__ dst,
    const int* __restrict__ eidx,
    const float* __restrict__ We_enc, const float* __restrict__ be_enc,
    const float* __restrict__ We_core,
    const float* __restrict__ We_dec, const float* __restrict__ be_dec,
    const float* __restrict__ We_out, const float* __restrict__ be_out,
    float* __restrict__ out_e, int E) {
    __shared__ __align__(16) float sWa[16][16];   // e1 weights (step1: e1+ec combined)
    __shared__ __align__(16) float sWb[16][16];   // ec weights (step2)
    __shared__ __align__(16) float sWdec[16][16];
    __shared__ float sWoutT[2][16];
    __shared__ float sGproj[256];
    __shared__ float sWenc[16], sBenc[16], sBdec[16], sBout[2];

    int t = threadIdx.x;
    {
        int k = t >> 4, h = t & 15;
        if (STEP == 1) {
            sWa[k][h] = We_core[k * 16 + h] + We_core[(16 + k) * 16 + h];
            sWb[k][h] = 0.f;
        } else {
            sWa[k][h] = We_core[k * 16 + h];
            sWb[k][h] = We_core[(16 + k) * 16 + h];
        }
        sWdec[k][h] = We_dec[k * 16 + h];
        sGproj[t] = d_small[GPE + t];
    }
    if (t < 16) {
        sWenc[t] = We_enc[t]; sBenc[t] = be_enc[t]; sBdec[t] = be_dec[t];
        sWoutT[0][t] = We_out[2 * t]; sWoutT[1][t] = We_out[2 * t + 1];
    }
    if (t < 2) sBout[t] = be_out[t];
    __syncthreads();

    float eAgg[16];
#pragma unroll
    for (int h = 0; h < 16; h++) eAgg[h] = 0.f;
    int curB = -1;

    int base = blockIdx.x * (256 * EPT);
#pragma unroll
    for (int it = 0; it < EPT; ++it) {
        int i = base + it * 256 + t;
        if (i < E) {
            float ev = e[i];
            int s = src[i], d = dst[i], b = eidx[i];

            float acc[16];
            const float4* ps = reinterpret_cast<const float4*>(d_projS + (size_t)s * 16);
            const float4* pd = reinterpret_cast<const float4*>(d_projD + (size_t)d * 16);
            const float* gp = &sGproj[b * 16];
#pragma unroll
            for (int q = 0; q < 4; q++) {
                float4 a = ps[q], c = pd[q];
                acc[4 * q + 0] = a.x + c.x + gp[4 * q + 0];
                acc[4 * q + 1] = a.y + c.y + gp[4 * q + 1];
                acc[4 * q + 2] = a.z + c.z + gp[4 * q + 2];
                acc[4 * q + 3] = a.w + c.w + gp[4 * q + 3];
            }
            float e1[16];
#pragma unroll
            for (int h = 0; h < 16; h++)
                e1[h] = fmaxf(fmaf(ev, sWenc[h], sBenc[h]), 0.f);
            mac16(sWa, e1, acc);
            if (STEP == 2) {
                float ec[16];
                const float4* pe = reinterpret_cast<const float4*>(d_ec + (size_t)i * 16);
#pragma unroll
                for (int q = 0; q < 4; q++) {
                    float4 v = pe[q];
                    ec[4 * q] = v.x; ec[4 * q + 1] = v.y; ec[4 * q + 2] = v.z; ec[4 * q + 3] = v.w;
                }
                mac16(sWb, ec, acc);
            }
#pragma unroll
            for (int h = 0; h < 16; h++) acc[h] = fmaxf(acc[h], 0.f);  // e_new

            if (STEP == 1) {
                float4* po = reinterpret_cast<float4*>(d_ec + (size_t)i * 16);
#pragma unroll
                for (int q = 0; q < 4; q++)
                    po[q] = make_float4(acc[4 * q], acc[4 * q + 1], acc[4 * q + 2], acc[4 * q + 3]);
            }
            // scatter-sum onto destination nodes (vector REDs)
            {
                float* p = d_aggE + (size_t)d * 16;
                RED4(p,      acc[0],  acc[1],  acc[2],  acc[3]);
                RED4(p + 4,  acc[4],  acc[5],  acc[6],  acc[7]);
                RED4(p + 8,  acc[8],  acc[9],  acc[10], acc[11]);
                RED4(p + 12, acc[12], acc[13], acc[14], acc[15]);
            }
            // per-graph edge aggregation: register accumulate (sorted edge_idx)
            if (b != curB) {
                if (curB >= 0) lane_flush16(curB, eAgg, d_small + EAGG);
                curB = b;
#pragma unroll
                for (int h = 0; h < 16; h++) eAgg[h] = 0.f;
            }
#pragma unroll
            for (int h = 0; h < 16; h++) eAgg[h] += acc[h];

            // decoder + output head fused
            float ed[16];
#pragma unroll
            for (int h = 0; h < 16; h++) ed[h] = sBdec[h];
            mac16(sWdec, acc, ed);
#pragma unroll
            for (int h = 0; h < 16; h++) ed[h] = fmaxf(ed[h], 0.f);
            float o0 = sBout[0], o1 = sBout[1];
#pragma unroll
            for (int k = 0; k < 16; k++) {
                o0 = fmaf(ed[k], sWoutT[0][k], o0);
                o1 = fmaf(ed[k], sWoutT[1][k], o1);
            }
            reinterpret_cast<float2*>(out_e)[(size_t)(STEP - 1) * E + i] = make_float2(o0, o1);
        }
    }
    warp_flush16(curB, eAgg, d_small + EAGG);
}

// ---------------- node kernel (node core + decoder + out + proj update) ----------------
template <int STEP>
__global__ void __launch_bounds__(256) node_kernel(
    const float* __restrict__ x, const int* __restrict__ nidx,
    const float* __restrict__ Wx_enc, const float* __restrict__ bx_enc,
    const float* __restrict__ Wx_core, const float* __restrict__ We_core,
    const float* __restrict__ Wx_dec, const float* __restrict__ bx_dec,
    const float* __restrict__ Wx_out, const float* __restrict__ bx_out,
    float* __restrict__ out_x, int N) {
    __shared__ __align__(16) float sWxA[16][16], sWxB[16][16], sWagg[16][16], sWdec[16][16];
    __shared__ __align__(16) float sWSt[16][16], sWSb[16][16], sWDt[16][16], sWDb[16][16];
    __shared__ float sGprojX[256], sWoutT[2][16];
    __shared__ float sWenc[16], sBenc[16], sBdec[16], sBout[2];

    int t = threadIdx.x, k = t >> 4, h = t & 15;
    if (STEP == 1) {
        sWxA[k][h] = Wx_core[k * 16 + h] + Wx_core[(16 + k) * 16 + h];
        sWxB[k][h] = 0.f;
        sWSt[k][h] = We_core[(32 + k) * 16 + h];
        sWSb[k][h] = We_core[(48 + k) * 16 + h];
        sWDt[k][h] = We_core[(64 + k) * 16 + h];
        sWDb[k][h] = We_core[(80 + k) * 16 + h];
    } else {
        sWxA[k][h] = Wx_core[k * 16 + h];
        sWxB[k][h] = Wx_core[(16 + k) * 16 + h];
    }
    sWagg[k][h] = Wx_core[(32 + k) * 16 + h];
    sWdec[k][h] = Wx_dec[k * 16 + h];
    sGprojX[t] = d_small[GPX + t];
    if (t < 16) {
        sWenc[t] = Wx_enc[t]; sBenc[t] = bx_enc[t]; sBdec[t] = bx_dec[t];
        sWoutT[0][t] = Wx_out[2 * t]; sWoutT[1][t] = Wx_out[2 * t + 1];
    }
    if (t < 2) sBout[t] = bx_out[t];
    __syncthreads();

    int n = blockIdx.x * 256 + t;
    float xnew[16];
#pragma unroll
    for (int hh = 0; hh < 16; hh++) xnew[hh] = 0.f;
    int b = -1;

    if (n < N) {
        b = nidx[n];
        float xv = x[n];
        float x1[16];
#pragma unroll
        for (int hh = 0; hh < 16; hh++) x1[hh] = fmaxf(fmaf(xv, sWenc[hh], sBenc[hh]), 0.f);
        float acc[16];
        const float* gp = &sGprojX[b * 16];
#pragma unroll
        for (int hh = 0; hh < 16; hh++) acc[hh] = gp[hh];
        mac16(sWxA, x1, acc);
        if (STEP == 2) {
            float xc[16];
            const float4* pc = reinterpret_cast<const float4*>(d_xc + (size_t)n * 16);
#pragma unroll
            for (int q = 0; q < 4; q++) {
                float4 v = pc[q];
                xc[4 * q] = v.x; xc[4 * q + 1] = v.y; xc[4 * q + 2] = v.z; xc[4 * q + 3] = v.w;
            }
            mac16(sWxB, xc, acc);
        }
        float inv = 1.0f / fmaxf(d_counts[n], 1.0f);
        float am[16];
        const float4* pa = reinterpret_cast<const float4*>(d_aggE + (size_t)n * 16);
#pragma unroll
        for (int q = 0; q < 4; q++) {
            float4 v = pa[q];
            am[4 * q] = v.x * inv; am[4 * q + 1] = v.y * inv;
            am[4 * q + 2] = v.z * inv; am[4 * q + 3] = v.w * inv;
        }
        mac16(sWagg, am, acc);
#pragma unroll
        for (int hh = 0; hh < 16; hh++) xnew[hh] = fmaxf(acc[hh], 0.f);

        if (STEP == 1) {
            float4* pc = reinterpret_cast<float4*>(d_xc + (size_t)n * 16);
#pragma unroll
            for (int q = 0; q < 4; q++)
                pc[q] = make_float4(xnew[4 * q], xnew[4 * q + 1], xnew[4 * q + 2], xnew[4 * q + 3]);
            // projections for next step's edge gathers: x_in = [x1, xnew]
            float psv[16], pdv[16];
#pragma unroll
            for (int hh = 0; hh < 16; hh++) { psv[hh] = 0.f; pdv[hh] = 0.f; }
            mac16(sWSt, x1, psv);  mac16(sWSb, xnew, psv);
            mac16(sWDt, x1, pdv);  mac16(sWDb, xnew, pdv);
            float4* os = reinterpret_cast<float4*>(d_projS + (size_t)n * 16);
            float4* od = reinterpret_cast<float4*>(d_projD + (size_t)n * 16);
#pragma unroll
            for (int q = 0; q < 4; q++) {
                os[q] = make_float4(psv[4 * q], psv[4 * q + 1], psv[4 * q + 2], psv[4 * q + 3]);
                od[q] = make_float4(pdv[4 * q], pdv[4 * q + 1], pdv[4 * q + 2], pdv[4 * q + 3]);
            }
        }
        // decoder + output head
        float xd[16];
#pragma unroll
        for (int hh = 0; hh < 16; hh++) xd[hh] = sBdec[hh];
        mac16(sWdec, xnew, xd);
#pragma unroll
        for (int hh = 0; hh < 16; hh++) xd[hh] = fmaxf(xd[hh], 0.f);
        float o0 = sBout[0], o1 = sBout[1];
#pragma unroll
        for (int kk = 0; kk < 16; kk++) {
            o0 = fmaf(xd[kk], sWoutT[0][kk], o0);
            o1 = fmaf(xd[kk], sWoutT[1][kk], o1);
        }
        reinterpret_cast<float2*>(out_x)[(size_t)(STEP - 1) * N + n] = make_float2(o0, o1);
    }
    // per-graph node aggregation (sorted node_idx)
    warp_flush16(b, xnew, d_small + NAGG);
}

// ---------------- global kernel ----------------
template <int STEP>
__global__ void global_kernel(
    const float* __restrict__ Wg_core, const float* __restrict__ bg_core,
    const float* __restrict__ Wg_dec, const float* __restrict__ bg_dec,
    const float* __restrict__ Wg_out, const float* __restrict__ bg_out,
    const float* __restrict__ We_core, const float* __restrict__ be_core,
    const float* __restrict__ Wx_core, const float* __restrict__ bx_core,
    float* __restrict__ out_g, int B) {
    int t = threadIdx.x;
    if (t < B) {
        float g1 = d_small[G1O + t], gc = d_small[GCO + t];
        float acc = bg_core[0] + g1 * Wg_core[0] + gc * Wg_core[1];
#pragma unroll
        for (int h = 0; h < 16; h++) acc = fmaf(d_small[NAGG + t * 16 + h], Wg_core[2 + h], acc);
#pragma unroll
        for (int h = 0; h < 16; h++) acc = fmaf(d_small[EAGG + t * 16 + h], Wg_core[18 + h], acc);
        float gn = fmaxf(acc, 0.f);
        d_small[GCO + t] = gn;
        float gd = fmaxf(fmaf(gn, Wg_dec[0], bg_dec[0]), 0.f);
        out_g[(STEP - 1) * B + t] = fmaf(gd, Wg_out[0], bg_out[0]);
    }
    __syncthreads();
    if (STEP == 1 && t < B * 16) {
        int b = t >> 4, h = t & 15;
        float g1 = d_small[G1O + b], gn = d_small[GCO + b];
        d_small[GPE + t] = fmaf(g1, We_core[96 * 16 + h], fmaf(gn, We_core[97 * 16 + h], be_core[h]));
        d_small[GPX + t] = fmaf(g1, Wx_core[48 * 16 + h], fmaf(gn, Wx_core[49 * 16 + h], bx_core[h]));
    }
}

// ---------------- launch ----------------
extern "C" void kernel_launch(void* const* d_in, const int* in_sizes, int n_in,
                              void* d_out, int out_size) {
    const float* x       = (const float*)d_in[0];
    const float* e       = (const float*)d_in[1];
    const float* g       = (const float*)d_in[2];
    const float* We_enc  = (const float*)d_in[3];
    const float* be_enc  = (const float*)d_in[4];
    const float* Wx_enc  = (const float*)d_in[5];
    const float* bx_enc  = (const float*)d_in[6];
    const float* Wg_enc  = (const float*)d_in[7];
    const float* bg_enc  = (const float*)d_in[8];
    const float* We_core = (const float*)d_in[9];
    const float* be_core = (const float*)d_in[10];
    const float* Wx_core = (const float*)d_in[11];
    const float* bx_core = (const float*)d_in[12];
    const float* Wg_core = (const float*)d_in[13];
    const float* bg_core = (const float*)d_in[14];
    const float* We_dec  = (const float*)d_in[15];
    const float* be_dec  = (const float*)d_in[16];
    const float* Wx_dec  = (const float*)d_in[17];
    const float* bx_dec  = (const float*)d_in[18];
    const float* Wg_dec  = (const float*)d_in[19];
    const float* bg_dec  = (const float*)d_in[20];
    const float* We_out  = (const float*)d_in[21];
    const float* be_out  = (const float*)d_in[22];
    const float* Wx_out  = (const float*)d_in[23];
    const float* bx_out  = (const float*)d_in[24];
    const float* Wg_out  = (const float*)d_in[25];
    const float* bg_out  = (const float*)d_in[26];
    const int*   edges   = (const int*)d_in[27];
    const int*   nidx    = (const int*)d_in[28];
    const int*   eidx    = (const int*)d_in[29];

    int N = in_sizes[0];
    int E = in_sizes[1];
    int B = in_sizes[2];
    float* out = (float*)d_out;
    float* out_e = out;
    float* out_x = out + (size_t)4 * E;              // 2 steps * E * 2
    float* out_g = out + (size_t)4 * E + (size_t)4 * N;

    const int* src = edges;
    const int* dst = edges + E;

    void *pCounts, *pAggE, *pSmall;
    cudaGetSymbolAddress(&pCounts, d_counts);
    cudaGetSymbolAddress(&pAggE, d_aggE);
    cudaGetSymbolAddress(&pSmall, d_small);

    cudaMemsetAsync(pCounts, 0, (size_t)N * sizeof(float), 0);
    cudaMemsetAsync(pAggE, 0, (size_t)N * 16 * sizeof(float), 0);
    cudaMemsetAsync((char*)pSmall + NAGG * sizeof(float), 0, 512 * sizeof(float), 0);

    count_kernel<<<(E + 255) / 256, 256>>>(dst, E);
    setup_node_kernel<<<(N + 255) / 256, 256>>>(x, Wx_enc, bx_enc, We_core, N);
    setup_global_kernel<<<1, 256>>>(g, Wg_enc, bg_enc, We_core, be_core, Wx_core, bx_core, B);

    int egrid = (E + 256 * EPT - 1) / (256 * EPT);
    int ngrid = (N + 255) / 256;

    // ---- step 1 ----
    edge_kernel<1><<<egrid, 256>>>(e, src, dst, eidx, We_enc, be_enc, We_core,
                                   We_dec, be_dec, We_out, be_out, out_e, E);
    node_kernel<1><<<ngrid, 256>>>(x, nidx, Wx_enc, bx_enc, Wx_core, We_core,
                                   Wx_dec, bx_dec, Wx_out, bx_out, out_x, N);
    global_kernel<1><<<1, 256>>>(Wg_core, bg_core, Wg_dec, bg_dec, Wg_out, bg_out,
                                 We_core, be_core, Wx_core, bx_core, out_g, B);

    cudaMemsetAsync(pAggE, 0, (size_t)N * 16 * sizeof(float), 0);
    cudaMemsetAsync((char*)pSmall + NAGG * sizeof(float), 0, 512 * sizeof(float), 0);

    // ---- step 2 ----
    edge_kernel<2><<<egrid, 256>>>(e, src, dst, eidx, We_enc, be_enc, We_core,
                                   We_dec, be_dec, We_out, be_out, out_e, E);
    node_kernel<2><<<ngrid, 256>>>(x, nidx, Wx_enc, bx_enc, Wx_core, We_core,
                                   Wx_dec, bx_dec, Wx_out, bx_out, out_x, N);
    global_kernel<2><<<1, 256>>>(Wg_core, bg_core, Wg_dec, bg_dec, Wg_out, bg_out,
                                 We_core, be_core, Wx_core, bx_core, out_g, B);
}

// round 2
// speedup vs baseline: 1.2378x; 1.2378x over previous
#include <cuda_runtime.h>
#include <cuda_fp16.h>
#include <cstdint>

// ---------------- problem constants ----------------
#define MAXN 100000
#define MAXE 1000000
#define NB   16
#define EPT  8

// d_small layout (floats)
#define GPE  0
#define GPX  256
#define NAGG 512
#define EAGG 768
#define G1O  1024
#define GCO  1040
#define SMALLN 1056

// ---------------- device scratch ----------------
__device__ __align__(128) __half d_projS[(size_t)MAXN * 16]; // fp16 gather tables
__device__ __align__(128) __half d_projD[(size_t)MAXN * 16];
__device__ __align__(128) __half2 d_ec[(size_t)8 * MAXE];    // SoA: [h2][edge]
__device__ __align__(128) float d_aggE[(size_t)MAXN * 16];
__device__ __align__(128) float d_xc[(size_t)MAXN * 16];
__device__ __align__(128) float d_counts[MAXN];
__device__ __align__(128) float d_small[SMALLN];

// ---------------- helpers ----------------
#define RED4(p, a, b, c, d) \
    asm volatile("red.global.add.v4.f32 [%0], {%1,%2,%3,%4};" \
                 :: "l"(p), "f"(a), "f"(b), "f"(c), "f"(d) : "memory")

__device__ __forceinline__ void unpack8(uint4 v, float* o) {
    float2 f;
    f = __half22float2(*reinterpret_cast<const __half2*>(&v.x)); o[0] = f.x; o[1] = f.y;
    f = __half22float2(*reinterpret_cast<const __half2*>(&v.y)); o[2] = f.x; o[3] = f.y;
    f = __half22float2(*reinterpret_cast<const __half2*>(&v.z)); o[4] = f.x; o[5] = f.y;
    f = __half22float2(*reinterpret_cast<const __half2*>(&v.w)); o[6] = f.x; o[7] = f.y;
}

__device__ __forceinline__ uint4 pack8(const float* s) {
    uint4 v;
    *reinterpret_cast<__half2*>(&v.x) = __floats2half2_rn(s[0], s[1]);
    *reinterpret_cast<__half2*>(&v.y) = __floats2half2_rn(s[2], s[3]);
    *reinterpret_cast<__half2*>(&v.z) = __floats2half2_rn(s[4], s[5]);
    *reinterpret_cast<__half2*>(&v.w) = __floats2half2_rn(s[6], s[7]);
    return v;
}

__device__ __forceinline__ void mac16(const float (*__restrict__ W)[16],
                                      const float* __restrict__ in,
                                      float* __restrict__ acc) {
#pragma unroll
    for (int k = 0; k < 16; k++) {
        float v = in[k];
        const float4* w = reinterpret_cast<const float4*>(&W[k][0]);
        float4 w0 = w[0], w1 = w[1], w2 = w[2], w3 = w[3];
        acc[0]  = fmaf(v, w0.x, acc[0]);  acc[1]  = fmaf(v, w0.y, acc[1]);
        acc[2]  = fmaf(v, w0.z, acc[2]);  acc[3]  = fmaf(v, w0.w, acc[3]);
        acc[4]  = fmaf(v, w1.x, acc[4]);  acc[5]  = fmaf(v, w1.y, acc[5]);
        acc[6]  = fmaf(v, w1.z, acc[6]);  acc[7]  = fmaf(v, w1.w, acc[7]);
        acc[8]  = fmaf(v, w2.x, acc[8]);  acc[9]  = fmaf(v, w2.y, acc[9]);
        acc[10] = fmaf(v, w2.z, acc[10]); acc[11] = fmaf(v, w2.w, acc[11]);
        acc[12] = fmaf(v, w3.x, acc[12]); acc[13] = fmaf(v, w3.y, acc[13]);
        acc[14] = fmaf(v, w3.z, acc[14]); acc[15] = fmaf(v, w3.w, acc[15]);
    }
}

__device__ __forceinline__ void lane_flush16(int b, const float* v, float* gbase) {
    float* p = gbase + b * 16;
    RED4(p,      v[0],  v[1],  v[2],  v[3]);
    RED4(p + 4,  v[4],  v[5],  v[6],  v[7]);
    RED4(p + 8,  v[8],  v[9],  v[10], v[11]);
    RED4(p + 12, v[12], v[13], v[14], v[15]);
}

__device__ __forceinline__ void warp_flush16(int curB, float* v, float* gbase) {
    const unsigned full = 0xffffffffu;
    int b0 = __shfl_sync(full, curB, 0);
    bool uni = __all_sync(full, (curB == b0) || (curB < 0));
    if (uni) {
#pragma unroll
        for (int h = 0; h < 16; h++) {
            float s = v[h];
            s += __shfl_xor_sync(full, s, 16);
            s += __shfl_xor_sync(full, s, 8);
            s += __shfl_xor_sync(full, s, 4);
            s += __shfl_xor_sync(full, s, 2);
            s += __shfl_xor_sync(full, s, 1);
            v[h] = s;
        }
        if (((threadIdx.x & 31) == 0) && b0 >= 0) lane_flush16(b0, v, gbase);
    } else if (curB >= 0) {
        lane_flush16(curB, v, gbase);
    }
}

// ---------------- setup kernels ----------------
__global__ void __launch_bounds__(256) setup_node_kernel(
    const float* __restrict__ x,
    const float* __restrict__ Wx_enc, const float* __restrict__ bx_enc,
    const float* __restrict__ We_core, int N) {
    __shared__ __align__(16) float sWS[16][16], sWD[16][16];
    __shared__ float sWenc[16], sBenc[16];
    int t = threadIdx.x, k = t >> 4, h = t & 15;
    sWS[k][h] = We_core[(32 + k) * 16 + h] + We_core[(48 + k) * 16 + h];
    sWD[k][h] = We_core[(64 + k) * 16 + h] + We_core[(80 + k) * 16 + h];
    if (t < 16) { sWenc[t] = Wx_enc[t]; sBenc[t] = bx_enc[t]; }
    __syncthreads();
    int n = blockIdx.x * 256 + t;
    if (n >= N) return;
    float xv = x[n];
    float x1[16];
#pragma unroll
    for (int hh = 0; hh < 16; hh++) x1[hh] = fmaxf(fmaf(xv, sWenc[hh], sBenc[hh]), 0.f);
    float ps[16], pd[16];
#pragma unroll
    for (int hh = 0; hh < 16; hh++) { ps[hh] = 0.f; pd[hh] = 0.f; }
    mac16(sWS, x1, ps);
    mac16(sWD, x1, pd);
    uint4* os = reinterpret_cast<uint4*>(d_projS + (size_t)n * 16);
    uint4* od = reinterpret_cast<uint4*>(d_projD + (size_t)n * 16);
    os[0] = pack8(ps); os[1] = pack8(ps + 8);
    od[0] = pack8(pd); od[1] = pack8(pd + 8);
}

__global__ void setup_global_kernel(
    const float* __restrict__ g,
    const float* __restrict__ Wg_enc, const float* __restrict__ bg_enc,
    const float* __restrict__ We_core, const float* __restrict__ be_core,
    const float* __restrict__ Wx_core, const float* __restrict__ bx_core, int B) {
    int t = threadIdx.x;
    if (t < B) {
        float g1 = fmaxf(fmaf(g[t], Wg_enc[0], bg_enc[0]), 0.f);
        d_small[G1O + t] = g1;
        d_small[GCO + t] = g1;
    }
    __syncthreads();
    if (t < B * 16) {
        int b = t >> 4, h = t & 15;
        float g1 = d_small[G1O + b];
        d_small[GPE + t] = fmaf(g1, We_core[96 * 16 + h] + We_core[97 * 16 + h], be_core[h]);
        d_small[GPX + t] = fmaf(g1, Wx_core[48 * 16 + h] + Wx_core[49 * 16 + h], bx_core[h]);
    }
}

// ---------------- edge kernel ----------------
template <int STEP>
__global__ void __launch_bounds__(256) edge_kernel(
    const float* __restrict__ e,
    const int* __restrict__ src, const int* __restrict__ dst,
    const int* __restrict__ eidx,
    const float* __restrict__ We_enc, const float* __restrict__ be_enc,
    const float* __restrict__ We_core,
    const float* __restrict__ We_dec, const float* __restrict__ be_dec,
    const float* __restrict__ We_out, const float* __restrict__ be_out,
    float* __restrict__ out_e, int E) {
    __shared__ __align__(16) float sWa[16][16];
    __shared__ __align__(16) float sWb[16][16];
    __shared__ __align__(16) float sWdec[16][16];
    __shared__ float sWoutT[2][16];
    __shared__ float sGproj[256];
    __shared__ float sWenc[16], sBenc[16], sBdec[16], sBout[2];

    int t = threadIdx.x;
    {
        int k = t >> 4, h = t & 15;
        if (STEP == 1) {
            sWa[k][h] = We_core[k * 16 + h] + We_core[(16 + k) * 16 + h];
            sWb[k][h] = 0.f;
        } else {
            sWa[k][h] = We_core[k * 16 + h];
            sWb[k][h] = We_core[(16 + k) * 16 + h];
        }
        sWdec[k][h] = We_dec[k * 16 + h];
        sGproj[t] = d_small[GPE + t];
    }
    if (t < 16) {
        sWenc[t] = We_enc[t]; sBenc[t] = be_enc[t]; sBdec[t] = be_dec[t];
        sWoutT[0][t] = We_out[2 * t]; sWoutT[1][t] = We_out[2 * t + 1];
    }
    if (t < 2) sBout[t] = be_out[t];
    __syncthreads();

    float eAgg[16];
#pragma unroll
    for (int h = 0; h < 16; h++) eAgg[h] = 0.f;
    int curB = -1;

    int base = blockIdx.x * (256 * EPT);
#pragma unroll
    for (int it = 0; it < EPT; ++it) {
        int i = base + it * 256 + t;
        if (i < E) {
            float ev = e[i];
            int s = src[i], d = dst[i], b = eidx[i];

            // fp16 gathers: 2x LDG.128 per table
            const uint4* ps = reinterpret_cast<const uint4*>(d_projS + (size_t)s * 16);
            const uint4* pd = reinterpret_cast<const uint4*>(d_projD + (size_t)d * 16);
            uint4 s0 = ps[0], s1 = ps[1], d0 = pd[0], d1 = pd[1];
            float psf[16], pdf[16];
            unpack8(s0, psf); unpack8(s1, psf + 8);
            unpack8(d0, pdf); unpack8(d1, pdf + 8);

            float acc[16];
            const float* gp = &sGproj[b * 16];
#pragma unroll
            for (int h = 0; h < 16; h++) acc[h] = psf[h] + pdf[h] + gp[h];

            float e1[16];
#pragma unroll
            for (int h = 0; h < 16; h++)
                e1[h] = fmaxf(fmaf(ev, sWenc[h], sBenc[h]), 0.f);
            mac16(sWa, e1, acc);
            if (STEP == 2) {
                float ec[16];
#pragma unroll
                for (int h2 = 0; h2 < 8; h2++) {
                    float2 f = __half22float2(d_ec[(size_t)h2 * MAXE + i]);
                    ec[2 * h2] = f.x; ec[2 * h2 + 1] = f.y;
                }
                mac16(sWb, ec, acc);
            }
#pragma unroll
            for (int h = 0; h < 16; h++) acc[h] = fmaxf(acc[h], 0.f);  // e_new

            if (STEP == 1) {
                // SoA fp16 store, fully coalesced
#pragma unroll
                for (int h2 = 0; h2 < 8; h2++)
                    d_ec[(size_t)h2 * MAXE + i] = __floats2half2_rn(acc[2 * h2], acc[2 * h2 + 1]);
                // per-dst edge count (replaces count_kernel)
                asm volatile("red.global.add.f32 [%0], %1;"
                             :: "l"(d_counts + d), "f"(1.0f) : "memory");
            }
            // scatter-sum onto destination nodes
            {
                float* p = d_aggE + (size_t)d * 16;
                RED4(p,      acc[0],  acc[1],  acc[2],  acc[3]);
                RED4(p + 4,  acc[4],  acc[5],  acc[6],  acc[7]);
                RED4(p + 8,  acc[8],  acc[9],  acc[10], acc[11]);
                RED4(p + 12, acc[12], acc[13], acc[14], acc[15]);
            }
            // per-graph edge aggregation
            if (b != curB) {
                if (curB >= 0) lane_flush16(curB, eAgg, d_small + EAGG);
                curB = b;
#pragma unroll
                for (int h = 0; h < 16; h++) eAgg[h] = 0.f;
            }
#pragma unroll
            for (int h = 0; h < 16; h++) eAgg[h] += acc[h];

            // decoder + output head
            float ed[16];
#pragma unroll
            for (int h = 0; h < 16; h++) ed[h] = sBdec[h];
            mac16(sWdec, acc, ed);
#pragma unroll
            for (int h = 0; h < 16; h++) ed[h] = fmaxf(ed[h], 0.f);
            float o0 = sBout[0], o1 = sBout[1];
#pragma unroll
            for (int k = 0; k < 16; k++) {
                o0 = fmaf(ed[k], sWoutT[0][k], o0);
                o1 = fmaf(ed[k], sWoutT[1][k], o1);
            }
            reinterpret_cast<float2*>(out_e)[(size_t)(STEP - 1) * E + i] = make_float2(o0, o1);
        }
    }
    warp_flush16(curB, eAgg, d_small + EAGG);
}

// ---------------- node kernel ----------------
template <int STEP>
__global__ void __launch_bounds__(256) node_kernel(
    const float* __restrict__ x, const int* __restrict__ nidx,
    const float* __restrict__ Wx_enc, const float* __restrict__ bx_enc,
    const float* __restrict__ Wx_core, const float* __restrict__ We_core,
    const float* __restrict__ Wx_dec, const float* __restrict__ bx_dec,
    const float* __restrict__ Wx_out, const float* __restrict__ bx_out,
    float* __restrict__ out_x, int N) {
    __shared__ __align__(16) float sWxA[16][16], sWxB[16][16], sWagg[16][16], sWdec[16][16];
    __shared__ __align__(16) float sWSt[16][16], sWSb[16][16], sWDt[16][16], sWDb[16][16];
    __shared__ float sGprojX[256], sWoutT[2][16];
    __shared__ float sWenc[16], sBenc[16], sBdec[16], sBout[2];

    int t = threadIdx.x, k = t >> 4, h = t & 15;
    if (STEP == 1) {
        sWxA[k][h] = Wx_core[k * 16 + h] + Wx_core[(16 + k) * 16 + h];
        sWxB[k][h] = 0.f;
        sWSt[k][h] = We_core[(32 + k) * 16 + h];
        sWSb[k][h] = We_core[(48 + k) * 16 + h];
        sWDt[k][h] = We_core[(64 + k) * 16 + h];
        sWDb[k][h] = We_core[(80 + k) * 16 + h];
    } else {
        sWxA[k][h] = Wx_core[k * 16 + h];
        sWxB[k][h] = Wx_core[(16 + k) * 16 + h];
    }
    sWagg[k][h] = Wx_core[(32 + k) * 16 + h];
    sWdec[k][h] = Wx_dec[k * 16 + h];
    sGprojX[t] = d_small[GPX + t];
    if (t < 16) {
        sWenc[t] = Wx_enc[t]; sBenc[t] = bx_enc[t]; sBdec[t] = bx_dec[t];
        sWoutT[0][t] = Wx_out[2 * t]; sWoutT[1][t] = Wx_out[2 * t + 1];
    }
    if (t < 2) sBout[t] = bx_out[t];
    __syncthreads();

    int n = blockIdx.x * 256 + t;
    float xnew[16];
#pragma unroll
    for (int hh = 0; hh < 16; hh++) xnew[hh] = 0.f;
    int b = -1;

    if (n < N) {
        b = nidx[n];
        float xv = x[n];
        float x1[16];
#pragma unroll
        for (int hh = 0; hh < 16; hh++) x1[hh] = fmaxf(fmaf(xv, sWenc[hh], sBenc[hh]), 0.f);
        float acc[16];
        const float* gp = &sGprojX[b * 16];
#pragma unroll
        for (int hh = 0; hh < 16; hh++) acc[hh] = gp[hh];
        mac16(sWxA, x1, acc);
        if (STEP == 2) {
            float xc[16];
            const float4* pc = reinterpret_cast<const float4*>(d_xc + (size_t)n * 16);
#pragma unroll
            for (int q = 0; q < 4; q++) {
                float4 v = pc[q];
                xc[4 * q] = v.x; xc[4 * q + 1] = v.y; xc[4 * q + 2] = v.z; xc[4 * q + 3] = v.w;
            }
            mac16(sWxB, xc, acc);
        }
        float inv = 1.0f / fmaxf(d_counts[n], 1.0f);
        float am[16];
        const float4* pa = reinterpret_cast<const float4*>(d_aggE + (size_t)n * 16);
#pragma unroll
        for (int q = 0; q < 4; q++) {
            float4 v = pa[q];
            am[4 * q] = v.x * inv; am[4 * q + 1] = v.y * inv;
            am[4 * q + 2] = v.z * inv; am[4 * q + 3] = v.w * inv;
        }
        mac16(sWagg, am, acc);
#pragma unroll
        for (int hh = 0; hh < 16; hh++) xnew[hh] = fmaxf(acc[hh], 0.f);

        if (STEP == 1) {
            float4* pc = reinterpret_cast<float4*>(d_xc + (size_t)n * 16);
#pragma unroll
            for (int q = 0; q < 4; q++)
                pc[q] = make_float4(xnew[4 * q], xnew[4 * q + 1], xnew[4 * q + 2], xnew[4 * q + 3]);
            float psv[16], pdv[16];
#pragma unroll
            for (int hh = 0; hh < 16; hh++) { psv[hh] = 0.f; pdv[hh] = 0.f; }
            mac16(sWSt, x1, psv);  mac16(sWSb, xnew, psv);
            mac16(sWDt, x1, pdv);  mac16(sWDb, xnew, pdv);
            uint4* os = reinterpret_cast<uint4*>(d_projS + (size_t)n * 16);
            uint4* od = reinterpret_cast<uint4*>(d_projD + (size_t)n * 16);
            os[0] = pack8(psv); os[1] = pack8(psv + 8);
            od[0] = pack8(pdv); od[1] = pack8(pdv + 8);
        }
        float xd[16];
#pragma unroll
        for (int hh = 0; hh < 16; hh++) xd[hh] = sBdec[hh];
        mac16(sWdec, xnew, xd);
#pragma unroll
        for (int hh = 0; hh < 16; hh++) xd[hh] = fmaxf(xd[hh], 0.f);
        float o0 = sBout[0], o1 = sBout[1];
#pragma unroll
        for (int kk = 0; kk < 16; kk++) {
            o0 = fmaf(xd[kk], sWoutT[0][kk], o0);
            o1 = fmaf(xd[kk], sWoutT[1][kk], o1);
        }
        reinterpret_cast<float2*>(out_x)[(size_t)(STEP - 1) * N + n] = make_float2(o0, o1);
    }
    warp_flush16(b, xnew, d_small + NAGG);
}

// ---------------- global kernel ----------------
template <int STEP>
__global__ void global_kernel(
    const float* __restrict__ Wg_core, const float* __restrict__ bg_core,
    const float* __restrict__ Wg_dec, const float* __restrict__ bg_dec,
    const float* __restrict__ Wg_out, const float* __restrict__ bg_out,
    const float* __restrict__ We_core, const float* __restrict__ be_core,
    const float* __restrict__ Wx_core, const float* __restrict__ bx_core,
    float* __restrict__ out_g, int B) {
    int t = threadIdx.x;
    if (t < B) {
        float g1 = d_small[G1O + t], gc = d_small[GCO + t];
        float acc = bg_core[0] + g1 * Wg_core[0] + gc * Wg_core[1];
#pragma unroll
        for (int h = 0; h < 16; h++) acc = fmaf(d_small[NAGG + t * 16 + h], Wg_core[2 + h], acc);
#pragma unroll
        for (int h = 0; h < 16; h++) acc = fmaf(d_small[EAGG + t * 16 + h], Wg_core[18 + h], acc);
        float gn = fmaxf(acc, 0.f);
        d_small[GCO + t] = gn;
        float gd = fmaxf(fmaf(gn, Wg_dec[0], bg_dec[0]), 0.f);
        out_g[(STEP - 1) * B + t] = fmaf(gd, Wg_out[0], bg_out[0]);
    }
    __syncthreads();
    if (STEP == 1 && t < B * 16) {
        int b = t >> 4, h = t & 15;
        float g1 = d_small[G1O + b], gn = d_small[GCO + b];
        d_small[GPE + t] = fmaf(g1, We_core[96 * 16 + h], fmaf(gn, We_core[97 * 16 + h], be_core[h]));
        d_small[GPX + t] = fmaf(g1, Wx_core[48 * 16 + h], fmaf(gn, Wx_core[49 * 16 + h], bx_core[h]));
    }
}

// ---------------- launch ----------------
extern "C" void kernel_launch(void* const* d_in, const int* in_sizes, int n_in,
                              void* d_out, int out_size) {
    const float* x       = (const float*)d_in[0];
    const float* e       = (const float*)d_in[1];
    const float* g       = (const float*)d_in[2];
    const float* We_enc  = (const float*)d_in[3];
    const float* be_enc  = (const float*)d_in[4];
    const float* Wx_enc  = (const float*)d_in[5];
    const float* bx_enc  = (const float*)d_in[6];
    const float* Wg_enc  = (const float*)d_in[7];
    const float* bg_enc  = (const float*)d_in[8];
    const float* We_core = (const float*)d_in[9];
    const float* be_core = (const float*)d_in[10];
    const float* Wx_core = (const float*)d_in[11];
    const float* bx_core = (const float*)d_in[12];
    const float* Wg_core = (const float*)d_in[13];
    const float* bg_core = (const float*)d_in[14];
    const float* We_dec  = (const float*)d_in[15];
    const float* be_dec  = (const float*)d_in[16];
    const float* Wx_dec  = (const float*)d_in[17];
    const float* bx_dec  = (const float*)d_in[18];
    const float* Wg_dec  = (const float*)d_in[19];
    const float* bg_dec  = (const float*)d_in[20];
    const float* We_out  = (const float*)d_in[21];
    const float* be_out  = (const float*)d_in[22];
    const float* Wx_out  = (const float*)d_in[23];
    const float* bx_out  = (const float*)d_in[24];
    const float* Wg_out  = (const float*)d_in[25];
    const float* bg_out  = (const float*)d_in[26];
    const int*   edges   = (const int*)d_in[27];
    const int*   nidx    = (const int*)d_in[28];
    const int*   eidx    = (const int*)d_in[29];

    int N = in_sizes[0];
    int E = in_sizes[1];
    int B = in_sizes[2];
    float* out = (float*)d_out;
    float* out_e = out;
    float* out_x = out + (size_t)4 * E;
    float* out_g = out + (size_t)4 * E + (size_t)4 * N;

    const int* src = edges;
    const int* dst = edges + E;

    void *pCounts, *pAggE, *pSmall;
    cudaGetSymbolAddress(&pCounts, d_counts);
    cudaGetSymbolAddress(&pAggE, d_aggE);
    cudaGetSymbolAddress(&pSmall, d_small);

    cudaMemsetAsync(pCounts, 0, (size_t)N * sizeof(float), 0);
    cudaMemsetAsync(pAggE, 0, (size_t)N * 16 * sizeof(float), 0);
    cudaMemsetAsync((char*)pSmall + NAGG * sizeof(float), 0, 512 * sizeof(float), 0);

    setup_node_kernel<<<(N + 255) / 256, 256>>>(x, Wx_enc, bx_enc, We_core, N);
    setup_global_kernel<<<1, 256>>>(g, Wg_enc, bg_enc, We_core, be_core, Wx_core, bx_core, B);

    int egrid = (E + 256 * EPT - 1) / (256 * EPT);
    int ngrid = (N + 255) / 256;

    // ---- step 1 ----
    edge_kernel<1><<<egrid, 256>>>(e, src, dst, eidx, We_enc, be_enc, We_core,
                                   We_dec, be_dec, We_out, be_out, out_e, E);
    node_kernel<1><<<ngrid, 256>>>(x, nidx, Wx_enc, bx_enc, Wx_core, We_core,
                                   Wx_dec, bx_dec, Wx_out, bx_out, out_x, N);
    global_kernel<1><<<1, 256>>>(Wg_core, bg_core, Wg_dec, bg_dec, Wg_out, bg_out,
                                 We_core, be_core, Wx_core, bx_core, out_g, B);

    cudaMemsetAsync(pAggE, 0, (size_t)N * 16 * sizeof(float), 0);
    cudaMemsetAsync((char*)pSmall + NAGG * sizeof(float), 0, 512 * sizeof(float), 0);

    // ---- step 2 ----
    edge_kernel<2><<<egrid, 256>>>(e, src, dst, eidx, We_enc, be_enc, We_core,
                                   We_dec, be_dec, We_out, be_out, out_e, E);
    node_kernel<2><<<ngrid, 256>>>(x, nidx, Wx_enc, bx_enc, Wx_core, We_core,
                                   Wx_dec, bx_dec, Wx_out, bx_out, out_x, N);
    global_kernel<2><<<1, 256>>>(Wg_core, bg_core, Wg_dec, bg_dec, Wg_out, bg_out,
                                 We_core, be_core, Wx_core, bx_core, out_g, B);
}

// round 3
// speedup vs baseline: 1.2465x; 1.0070x over previous
#include <cuda_runtime.h>
#include <cuda_fp16.h>
#include <cstdint>

// ---------------- problem constants ----------------
#define MAXN 100000
#define MAXE 1000000
#define NB   16
#define EPT  8

// d_small layout (floats)
#define GPE  0
#define GPX  256
#define NAGG 512
#define EAGG 768
#define G1O  1024
#define GCO  1040
#define SMALLN 1056

// ---------------- device scratch ----------------
__device__ __align__(128) __half d_projS[(size_t)MAXN * 16]; // fp16 gather tables
__device__ __align__(128) __half d_projD[(size_t)MAXN * 16];
__device__ __align__(128) __half2 d_ec[(size_t)8 * MAXE];    // SoA: [h2][edge]
__device__ __align__(128) float d_aggE[(size_t)MAXN * 16];
__device__ __align__(128) float d_xc[(size_t)MAXN * 16];
__device__ __align__(128) float d_counts[MAXN];
__device__ __align__(128) float d_small[SMALLN];

// ---------------- helpers ----------------
#define RED4(p, a, b, c, d) \
    asm volatile("red.global.add.v4.f32 [%0], {%1,%2,%3,%4};" \
                 :: "l"(p), "f"(a), "f"(b), "f"(c), "f"(d) : "memory")

__device__ __forceinline__ void unpack8(uint4 v, float* o) {
    float2 f;
    f = __half22float2(*reinterpret_cast<const __half2*>(&v.x)); o[0] = f.x; o[1] = f.y;
    f = __half22float2(*reinterpret_cast<const __half2*>(&v.y)); o[2] = f.x; o[3] = f.y;
    f = __half22float2(*reinterpret_cast<const __half2*>(&v.z)); o[4] = f.x; o[5] = f.y;
    f = __half22float2(*reinterpret_cast<const __half2*>(&v.w)); o[6] = f.x; o[7] = f.y;
}

__device__ __forceinline__ uint4 pack8(const float* s) {
    uint4 v;
    *reinterpret_cast<__half2*>(&v.x) = __floats2half2_rn(s[0], s[1]);
    *reinterpret_cast<__half2*>(&v.y) = __floats2half2_rn(s[2], s[3]);
    *reinterpret_cast<__half2*>(&v.z) = __floats2half2_rn(s[4], s[5]);
    *reinterpret_cast<__half2*>(&v.w) = __floats2half2_rn(s[6], s[7]);
    return v;
}

__device__ __forceinline__ void mac16(const float (*__restrict__ W)[16],
                                      const float* __restrict__ in,
                                      float* __restrict__ acc) {
#pragma unroll
    for (int k = 0; k < 16; k++) {
        float v = in[k];
        const float4* w = reinterpret_cast<const float4*>(&W[k][0]);
        float4 w0 = w[0], w1 = w[1], w2 = w[2], w3 = w[3];
        acc[0]  = fmaf(v, w0.x, acc[0]);  acc[1]  = fmaf(v, w0.y, acc[1]);
        acc[2]  = fmaf(v, w0.z, acc[2]);  acc[3]  = fmaf(v, w0.w, acc[3]);
        acc[4]  = fmaf(v, w1.x, acc[4]);  acc[5]  = fmaf(v, w1.y, acc[5]);
        acc[6]  = fmaf(v, w1.z, acc[6]);  acc[7]  = fmaf(v, w1.w, acc[7]);
        acc[8]  = fmaf(v, w2.x, acc[8]);  acc[9]  = fmaf(v, w2.y, acc[9]);
        acc[10] = fmaf(v, w2.z, acc[10]); acc[11] = fmaf(v, w2.w, acc[11]);
        acc[12] = fmaf(v, w3.x, acc[12]); acc[13] = fmaf(v, w3.y, acc[13]);
        acc[14] = fmaf(v, w3.z, acc[14]); acc[15] = fmaf(v, w3.w, acc[15]);
    }
}

__device__ __forceinline__ void lane_flush16(int b, const float* v, float* gbase) {
    float* p = gbase + b * 16;
    RED4(p,      v[0],  v[1],  v[2],  v[3]);
    RED4(p + 4,  v[4],  v[5],  v[6],  v[7]);
    RED4(p + 8,  v[8],  v[9],  v[10], v[11]);
    RED4(p + 12, v[12], v[13], v[14], v[15]);
}

__device__ __forceinline__ void warp_flush16(int curB, float* v, float* gbase) {
    const unsigned full = 0xffffffffu;
    int b0 = __shfl_sync(full, curB, 0);
    bool uni = __all_sync(full, (curB == b0) || (curB < 0));
    if (uni) {
#pragma unroll
        for (int h = 0; h < 16; h++) {
            float s = v[h];
            s += __shfl_xor_sync(full, s, 16);
            s += __shfl_xor_sync(full, s, 8);
            s += __shfl_xor_sync(full, s, 4);
            s += __shfl_xor_sync(full, s, 2);
            s += __shfl_xor_sync(full, s, 1);
            v[h] = s;
        }
        if (((threadIdx.x & 31) == 0) && b0 >= 0) lane_flush16(b0, v, gbase);
    } else if (curB >= 0) {
        lane_flush16(curB, v, gbase);
    }
}

// ---------------- setup kernels ----------------
__global__ void __launch_bounds__(256) setup_node_kernel(
    const float* __restrict__ x,
    const float* __restrict__ Wx_enc, const float* __restrict__ bx_enc,
    const float* __restrict__ We_core, int N) {
    __shared__ __align__(16) float sWS[16][16], sWD[16][16];
    __shared__ float sWenc[16], sBenc[16];
    int t = threadIdx.x, k = t >> 4, h = t & 15;
    sWS[k][h] = We_core[(32 + k) * 16 + h] + We_core[(48 + k) * 16 + h];
    sWD[k][h] = We_core[(64 + k) * 16 + h] + We_core[(80 + k) * 16 + h];
    if (t < 16) { sWenc[t] = Wx_enc[t]; sBenc[t] = bx_enc[t]; }
    __syncthreads();
    int n = blockIdx.x * 256 + t;
    if (n >= N) return;
    float xv = x[n];
    float x1[16];
#pragma unroll
    for (int hh = 0; hh < 16; hh++) x1[hh] = fmaxf(fmaf(xv, sWenc[hh], sBenc[hh]), 0.f);
    float ps[16], pd[16];
#pragma unroll
    for (int hh = 0; hh < 16; hh++) { ps[hh] = 0.f; pd[hh] = 0.f; }
    mac16(sWS, x1, ps);
    mac16(sWD, x1, pd);
    uint4* os = reinterpret_cast<uint4*>(d_projS + (size_t)n * 16);
    uint4* od = reinterpret_cast<uint4*>(d_projD + (size_t)n * 16);
    os[0] = pack8(ps); os[1] = pack8(ps + 8);
    od[0] = pack8(pd); od[1] = pack8(pd + 8);
}

__global__ void setup_global_kernel(
    const float* __restrict__ g,
    const float* __restrict__ Wg_enc, const float* __restrict__ bg_enc,
    const float* __restrict__ We_core, const float* __restrict__ be_core,
    const float* __restrict__ Wx_core, const float* __restrict__ bx_core, int B) {
    int t = threadIdx.x;
    if (t < B) {
        float g1 = fmaxf(fmaf(g[t], Wg_enc[0], bg_enc[0]), 0.f);
        d_small[G1O + t] = g1;
        d_small[GCO + t] = g1;
    }
    __syncthreads();
    if (t < B * 16) {
        int b = t >> 4, h = t & 15;
        float g1 = d_small[G1O + b];
        d_small[GPE + t] = fmaf(g1, We_core[96 * 16 + h] + We_core[97 * 16 + h], be_core[h]);
        d_small[GPX + t] = fmaf(g1, Wx_core[48 * 16 + h] + Wx_core[49 * 16 + h], bx_core[h]);
    }
}

// ---------------- edge kernel ----------------
template <int STEP>
__global__ void __launch_bounds__(256) edge_kernel(
    const float* __restrict__ e,
    const int* __restrict__ src, const int* __restrict__ dst,
    const int* __restrict__ eidx,
    const float* __restrict__ We_enc, const float* __restrict__ be_enc,
    const float* __restrict__ We_core,
    const float* __restrict__ We_dec, const float* __restrict__ be_dec,
    const float* __restrict__ We_out, const float* __restrict__ be_out,
    float* __restrict__ out_e, int E) {
    __shared__ __align__(16) float sWa[16][16];
    __shared__ __align__(16) float sWb[16][16];
    __shared__ __align__(16) float sWdec[16][16];
    __shared__ float sWoutT[2][16];
    __shared__ float sGproj[256];
    __shared__ float sWenc[16], sBenc[16], sBdec[16], sBout[2];

    int t = threadIdx.x;
    {
        int k = t >> 4, h = t & 15;
        if (STEP == 1) {
            sWa[k][h] = We_core[k * 16 + h] + We_core[(16 + k) * 16 + h];
            sWb[k][h] = 0.f;
        } else {
            sWa[k][h] = We_core[k * 16 + h];
            sWb[k][h] = We_core[(16 + k) * 16 + h];
        }
        sWdec[k][h] = We_dec[k * 16 + h];
        sGproj[t] = d_small[GPE + t];
    }
    if (t < 16) {
        sWenc[t] = We_enc[t]; sBenc[t] = be_enc[t]; sBdec[t] = be_dec[t];
        sWoutT[0][t] = We_out[2 * t]; sWoutT[1][t] = We_out[2 * t + 1];
    }
    if (t < 2) sBout[t] = be_out[t];
    __syncthreads();

    float eAgg[16];
#pragma unroll
    for (int h = 0; h < 16; h++) eAgg[h] = 0.f;
    int curB = -1;

    int base = blockIdx.x * (256 * EPT);
#pragma unroll
    for (int it = 0; it < EPT; ++it) {
        int i = base + it * 256 + t;
        if (i < E) {
            float ev = e[i];
            int s = src[i], d = dst[i], b = eidx[i];

            // fp16 gathers: 2x LDG.128 per table
            const uint4* ps = reinterpret_cast<const uint4*>(d_projS + (size_t)s * 16);
            const uint4* pd = reinterpret_cast<const uint4*>(d_projD + (size_t)d * 16);
            uint4 s0 = ps[0], s1 = ps[1], d0 = pd[0], d1 = pd[1];
            float psf[16], pdf[16];
            unpack8(s0, psf); unpack8(s1, psf + 8);
            unpack8(d0, pdf); unpack8(d1, pdf + 8);

            float acc[16];
            const float* gp = &sGproj[b * 16];
#pragma unroll
            for (int h = 0; h < 16; h++) acc[h] = psf[h] + pdf[h] + gp[h];

            float e1[16];
#pragma unroll
            for (int h = 0; h < 16; h++)
                e1[h] = fmaxf(fmaf(ev, sWenc[h], sBenc[h]), 0.f);
            mac16(sWa, e1, acc);
            if (STEP == 2) {
                float ec[16];
#pragma unroll
                for (int h2 = 0; h2 < 8; h2++) {
                    float2 f = __half22float2(d_ec[(size_t)h2 * MAXE + i]);
                    ec[2 * h2] = f.x; ec[2 * h2 + 1] = f.y;
                }
                mac16(sWb, ec, acc);
            }
#pragma unroll
            for (int h = 0; h < 16; h++) acc[h] = fmaxf(acc[h], 0.f);  // e_new

            if (STEP == 1) {
                // SoA fp16 store, fully coalesced
#pragma unroll
                for (int h2 = 0; h2 < 8; h2++)
                    d_ec[(size_t)h2 * MAXE + i] = __floats2half2_rn(acc[2 * h2], acc[2 * h2 + 1]);
                // per-dst edge count (replaces count_kernel)
                asm volatile("red.global.add.f32 [%0], %1;"
                             :: "l"(d_counts + d), "f"(1.0f) : "memory");
            }
            // scatter-sum onto destination nodes
            {
                float* p = d_aggE + (size_t)d * 16;
                RED4(p,      acc[0],  acc[1],  acc[2],  acc[3]);
                RED4(p + 4,  acc[4],  acc[5],  acc[6],  acc[7]);
                RED4(p + 8,  acc[8],  acc[9],  acc[10], acc[11]);
                RED4(p + 12, acc[12], acc[13], acc[14], acc[15]);
            }
            // per-graph edge aggregation
            if (b != curB) {
                if (curB >= 0) lane_flush16(curB, eAgg, d_small + EAGG);
                curB = b;
#pragma unroll
                for (int h = 0; h < 16; h++) eAgg[h] = 0.f;
            }
#pragma unroll
            for (int h = 0; h < 16; h++) eAgg[h] += acc[h];

            // decoder + output head
            float ed[16];
#pragma unroll
            for (int h = 0; h < 16; h++) ed[h] = sBdec[h];
            mac16(sWdec, acc, ed);
#pragma unroll
            for (int h = 0; h < 16; h++) ed[h] = fmaxf(ed[h], 0.f);
            float o0 = sBout[0], o1 = sBout[1];
#pragma unroll
            for (int k = 0; k < 16; k++) {
                o0 = fmaf(ed[k], sWoutT[0][k], o0);
                o1 = fmaf(ed[k], sWoutT[1][k], o1);
            }
            reinterpret_cast<float2*>(out_e)[(size_t)(STEP - 1) * E + i] = make_float2(o0, o1);
        }
    }
    warp_flush16(curB, eAgg, d_small + EAGG);
}

// ---------------- node kernel ----------------
template <int STEP>
__global__ void __launch_bounds__(256) node_kernel(
    const float* __restrict__ x, const int* __restrict__ nidx,
    const float* __restrict__ Wx_enc, const float* __restrict__ bx_enc,
    const float* __restrict__ Wx_core, const float* __restrict__ We_core,
    const float* __restrict__ Wx_dec, const float* __restrict__ bx_dec,
    const float* __restrict__ Wx_out, const float* __restrict__ bx_out,
    float* __restrict__ out_x, int N) {
    __shared__ __align__(16) float sWxA[16][16], sWxB[16][16], sWagg[16][16], sWdec[16][16];
    __shared__ __align__(16) float sWSt[16][16], sWSb[16][16], sWDt[16][16], sWDb[16][16];
    __shared__ float sGprojX[256], sWoutT[2][16];
    __shared__ float sWenc[16], sBenc[16], sBdec[16], sBout[2];

    int t = threadIdx.x, k = t >> 4, h = t & 15;
    if (STEP == 1) {
        sWxA[k][h] = Wx_core[k * 16 + h] + Wx_core[(16 + k) * 16 + h];
        sWxB[k][h] = 0.f;
        sWSt[k][h] = We_core[(32 + k) * 16 + h];
        sWSb[k][h] = We_core[(48 + k) * 16 + h];
        sWDt[k][h] = We_core[(64 + k) * 16 + h];
        sWDb[k][h] = We_core[(80 + k) * 16 + h];
    } else {
        sWxA[k][h] = Wx_core[k * 16 + h];
        sWxB[k][h] = Wx_core[(16 + k) * 16 + h];
    }
    sWagg[k][h] = Wx_core[(32 + k) * 16 + h];
    sWdec[k][h] = Wx_dec[k * 16 + h];
    sGprojX[t] = d_small[GPX + t];
    if (t < 16) {
        sWenc[t] = Wx_enc[t]; sBenc[t] = bx_enc[t]; sBdec[t] = bx_dec[t];
        sWoutT[0][t] = Wx_out[2 * t]; sWoutT[1][t] = Wx_out[2 * t + 1];
    }
    if (t < 2) sBout[t] = bx_out[t];
    __syncthreads();

    int n = blockIdx.x * 256 + t;
    float xnew[16];
#pragma unroll
    for (int hh = 0; hh < 16; hh++) xnew[hh] = 0.f;
    int b = -1;

    if (n < N) {
        b = nidx[n];
        float xv = x[n];
        float x1[16];
#pragma unroll
        for (int hh = 0; hh < 16; hh++) x1[hh] = fmaxf(fmaf(xv, sWenc[hh], sBenc[hh]), 0.f);
        float acc[16];
        const float* gp = &sGprojX[b * 16];
#pragma unroll
        for (int hh = 0; hh < 16; hh++) acc[hh] = gp[hh];
        mac16(sWxA, x1, acc);
        if (STEP == 2) {
            float xc[16];
            const float4* pc = reinterpret_cast<const float4*>(d_xc + (size_t)n * 16);
#pragma unroll
            for (int q = 0; q < 4; q++) {
                float4 v = pc[q];
                xc[4 * q] = v.x; xc[4 * q + 1] = v.y; xc[4 * q + 2] = v.z; xc[4 * q + 3] = v.w;
            }
            mac16(sWxB, xc, acc);
        }
        float inv = 1.0f / fmaxf(d_counts[n], 1.0f);
        float am[16];
        const float4* pa = reinterpret_cast<const float4*>(d_aggE + (size_t)n * 16);
#pragma unroll
        for (int q = 0; q < 4; q++) {
            float4 v = pa[q];
            am[4 * q] = v.x * inv; am[4 * q + 1] = v.y * inv;
            am[4 * q + 2] = v.z * inv; am[4 * q + 3] = v.w * inv;
        }
        mac16(sWagg, am, acc);
#pragma unroll
        for (int hh = 0; hh < 16; hh++) xnew[hh] = fmaxf(acc[hh], 0.f);

        if (STEP == 1) {
            float4* pc = reinterpret_cast<float4*>(d_xc + (size_t)n * 16);
#pragma unroll
            for (int q = 0; q < 4; q++)
                pc[q] = make_float4(xnew[4 * q], xnew[4 * q + 1], xnew[4 * q + 2], xnew[4 * q + 3]);
            float psv[16], pdv[16];
#pragma unroll
            for (int hh = 0; hh < 16; hh++) { psv[hh] = 0.f; pdv[hh] = 0.f; }
            mac16(sWSt, x1, psv);  mac16(sWSb, xnew, psv);
            mac16(sWDt, x1, pdv);  mac16(sWDb, xnew, pdv);
            uint4* os = reinterpret_cast<uint4*>(d_projS + (size_t)n * 16);
            uint4* od = reinterpret_cast<uint4*>(d_projD + (size_t)n * 16);
            os[0] = pack8(psv); os[1] = pack8(psv + 8);
            od[0] = pack8(pdv); od[1] = pack8(pdv + 8);
        }
        float xd[16];
#pragma unroll
        for (int hh = 0; hh < 16; hh++) xd[hh] = sBdec[hh];
        mac16(sWdec, xnew, xd);
#pragma unroll
        for (int hh = 0; hh < 16; hh++) xd[hh] = fmaxf(xd[hh], 0.f);
        float o0 = sBout[0], o1 = sBout[1];
#pragma unroll
        for (int kk = 0; kk < 16; kk++) {
            o0 = fmaf(xd[kk], sWoutT[0][kk], o0);
            o1 = fmaf(xd[kk], sWoutT[1][kk], o1);
        }
        reinterpret_cast<float2*>(out_x)[(size_t)(STEP - 1) * N + n] = make_float2(o0, o1);
    }
    warp_flush16(b, xnew, d_small + NAGG);
}

// ---------------- global kernel ----------------
template <int STEP>
__global__ void global_kernel(
    const float* __restrict__ Wg_core, const float* __restrict__ bg_core,
    const float* __restrict__ Wg_dec, const float* __restrict__ bg_dec,
    const float* __restrict__ Wg_out, const float* __restrict__ bg_out,
    const float* __restrict__ We_core, const float* __restrict__ be_core,
    const float* __restrict__ Wx_core, const float* __restrict__ bx_core,
    float* __restrict__ out_g, int B) {
    int t = threadIdx.x;
    if (t < B) {
        float g1 = d_small[G1O + t], gc = d_small[GCO + t];
        float acc = bg_core[0] + g1 * Wg_core[0] + gc * Wg_core[1];
#pragma unroll
        for (int h = 0; h < 16; h++) acc = fmaf(d_small[NAGG + t * 16 + h], Wg_core[2 + h], acc);
#pragma unroll
        for (int h = 0; h < 16; h++) acc = fmaf(d_small[EAGG + t * 16 + h], Wg_core[18 + h], acc);
        float gn = fmaxf(acc, 0.f);
        d_small[GCO + t] = gn;
        float gd = fmaxf(fmaf(gn, Wg_dec[0], bg_dec[0]), 0.f);
        out_g[(STEP - 1) * B + t] = fmaf(gd, Wg_out[0], bg_out[0]);
    }
    __syncthreads();
    if (STEP == 1 && t < B * 16) {
        int b = t >> 4, h = t & 15;
        float g1 = d_small[G1O + b], gn = d_small[GCO + b];
        d_small[GPE + t] = fmaf(g1, We_core[96 * 16 + h], fmaf(gn, We_core[97 * 16 + h], be_core[h]));
        d_small[GPX + t] = fmaf(g1, Wx_core[48 * 16 + h], fmaf(gn, Wx_core[49 * 16 + h], bx_core[h]));
    }
}

// ---------------- launch ----------------
extern "C" void kernel_launch(void* const* d_in, const int* in_sizes, int n_in,
                              void* d_out, int out_size) {
    const float* x       = (const float*)d_in[0];
    const float* e       = (const float*)d_in[1];
    const float* g       = (const float*)d_in[2];
    const float* We_enc  = (const float*)d_in[3];
    const float* be_enc  = (const float*)d_in[4];
    const float* Wx_enc  = (const float*)d_in[5];
    const float* bx_enc  = (const float*)d_in[6];
    const float* Wg_enc  = (const float*)d_in[7];
    const float* bg_enc  = (const float*)d_in[8];
    const float* We_core = (const float*)d_in[9];
    const float* be_core = (const float*)d_in[10];
    const float* Wx_core = (const float*)d_in[11];
    const float* bx_core = (const float*)d_in[12];
    const float* Wg_core = (const float*)d_in[13];
    const float* bg_core = (const float*)d_in[14];
    const float* We_dec  = (const float*)d_in[15];
    const float* be_dec  = (const float*)d_in[16];
    const float* Wx_dec  = (const float*)d_in[17];
    const float* bx_dec  = (const float*)d_in[18];
    const float* Wg_dec  = (const float*)d_in[19];
    const float* bg_dec  = (const float*)d_in[20];
    const float* We_out  = (const float*)d_in[21];
    const float* be_out  = (const float*)d_in[22];
    const float* Wx_out  = (const float*)d_in[23];
    const float* bx_out  = (const float*)d_in[24];
    const float* Wg_out  = (const float*)d_in[25];
    const float* bg_out  = (const float*)d_in[26];
    const int*   edges   = (const int*)d_in[27];
    const int*   nidx    = (const int*)d_in[28];
    const int*   eidx    = (const int*)d_in[29];

    int N = in_sizes[0];
    int E = in_sizes[1];
    int B = in_sizes[2];
    float* out = (float*)d_out;
    float* out_e = out;
    float* out_x = out + (size_t)4 * E;
    float* out_g = out + (size_t)4 * E + (size_t)4 * N;

    const int* src = edges;
    const int* dst = edges + E;

    void *pCounts, *pAggE, *pSmall;
    cudaGetSymbolAddress(&pCounts, d_counts);
    cudaGetSymbolAddress(&pAggE, d_aggE);
    cudaGetSymbolAddress(&pSmall, d_small);

    cudaMemsetAsync(pCounts, 0, (size_t)N * sizeof(float), 0);
    cudaMemsetAsync(pAggE, 0, (size_t)N * 16 * sizeof(float), 0);
    cudaMemsetAsync((char*)pSmall + NAGG * sizeof(float), 0, 512 * sizeof(float), 0);

    setup_node_kernel<<<(N + 255) / 256, 256>>>(x, Wx_enc, bx_enc, We_core, N);
    setup_global_kernel<<<1, 256>>>(g, Wg_enc, bg_enc, We_core, be_core, Wx_core, bx_core, B);

    int egrid = (E + 256 * EPT - 1) / (256 * EPT);
    int ngrid = (N + 255) / 256;

    // ---- step 1 ----
    edge_kernel<1><<<egrid, 256>>>(e, src, dst, eidx, We_enc, be_enc, We_core,
                                   We_dec, be_dec, We_out, be_out, out_e, E);
    node_kernel<1><<<ngrid, 256>>>(x, nidx, Wx_enc, bx_enc, Wx_core, We_core,
                                   Wx_dec, bx_dec, Wx_out, bx_out, out_x, N);
    global_kernel<1><<<1, 256>>>(Wg_core, bg_core, Wg_dec, bg_dec, Wg_out, bg_out,
                                 We_core, be_core, Wx_core, bx_core, out_g, B);

    cudaMemsetAsync(pAggE, 0, (size_t)N * 16 * sizeof(float), 0);
    cudaMemsetAsync((char*)pSmall + NAGG * sizeof(float), 0, 512 * sizeof(float), 0);

    // ---- step 2 ----
    edge_kernel<2><<<egrid, 256>>>(e, src, dst, eidx, We_enc, be_enc, We_core,
                                   We_dec, be_dec, We_out, be_out, out_e, E);
    node_kernel<2><<<ngrid, 256>>>(x, nidx, Wx_enc, bx_enc, Wx_core, We_core,
                                   Wx_dec, bx_dec, Wx_out, bx_out, out_x, N);
    global_kernel<2><<<1, 256>>>(Wg_core, bg_core, Wg_dec, bg_dec, Wg_out, bg_out,
                                 We_core, be_core, Wx_core, bx_core, out_g, B);
}

// round 4
// speedup vs baseline: 1.5465x; 1.2407x over previous
#include <cuda_runtime.h>
#include <cuda_fp16.h>
#include <cstdint>

typedef unsigned long long u64;
typedef unsigned int u32;

// ---------------- problem constants ----------------
#define MAXN 100000
#define MAXE 1000000
#define NB   16
#define EPT  8

// d_small layout (floats)
#define GPE  0
#define GPX  256
#define NAGG 512
#define EAGG 768
#define G1O  1024
#define GCO  1040
#define SMALLN 1056

// ---------------- device scratch ----------------
__device__ __align__(128) __half d_projS[(size_t)MAXN * 16];
__device__ __align__(128) __half d_projD[(size_t)MAXN * 16];
__device__ __align__(128) __half2 d_ec[(size_t)8 * MAXE];     // SoA: [h2][edge]
__device__ __align__(128) __half2 d_aggE2[(size_t)MAXN * 8];  // fp16 scatter target
__device__ __align__(128) float d_xc[(size_t)MAXN * 16];
__device__ __align__(128) float d_counts[MAXN];
__device__ __align__(128) float d_small[SMALLN];

// ---------------- f32x2 helpers ----------------
__device__ __forceinline__ u64 pack2(float lo, float hi) {
    u64 r; asm("mov.b64 %0,{%1,%2};" : "=l"(r) : "f"(lo), "f"(hi)); return r;
}
__device__ __forceinline__ void unpack2(u64 v, float& lo, float& hi) {
    asm("mov.b64 {%0,%1},%2;" : "=f"(lo), "=f"(hi) : "l"(v));
}
__device__ __forceinline__ u64 fma2(u64 a, u64 b, u64 c) {
    u64 r; asm("fma.rn.f32x2 %0,%1,%2,%3;" : "=l"(r) : "l"(a), "l"(b), "l"(c)); return r;
}
__device__ __forceinline__ u64 add2(u64 a, u64 b) {
    u64 r; asm("add.rn.f32x2 %0,%1,%2;" : "=l"(r) : "l"(a), "l"(b)); return r;
}
// half2 (as u32) -> packed f32x2
__device__ __forceinline__ u64 h2f2(u32 u) {
    __half2 h = *reinterpret_cast<__half2*>(&u);
    float2 f = __half22float2(h);
    return pack2(f.x, f.y);
}
__device__ __forceinline__ u32 f2h2u(float a, float b) {
    __half2 h = __floats2half2_rn(a, b);
    return *reinterpret_cast<u32*>(&h);
}

// acc2[8] += in[16] @ W2 (W2[k][j] packs columns 2j,2j+1 of row k)
__device__ __forceinline__ void mac16_2(const u64 (*__restrict__ W2)[8],
                                        const float* __restrict__ in,
                                        u64* __restrict__ acc2) {
#pragma unroll
    for (int k = 0; k < 16; k++) {
        u64 v2 = pack2(in[k], in[k]);
#pragma unroll
        for (int j = 0; j < 8; j++) acc2[j] = fma2(v2, W2[k][j], acc2[j]);
    }
}

// scalar-table mac for setup kernel
__device__ __forceinline__ void mac16(const float (*__restrict__ W)[16],
                                      const float* __restrict__ in,
                                      float* __restrict__ acc) {
#pragma unroll
    for (int k = 0; k < 16; k++) {
        float v = in[k];
#pragma unroll
        for (int h = 0; h < 16; h++) acc[h] = fmaf(v, W[k][h], acc[h]);
    }
}

__device__ __forceinline__ uint4 pack8h(const float* s) {
    uint4 v;
    v.x = f2h2u(s[0], s[1]); v.y = f2h2u(s[2], s[3]);
    v.z = f2h2u(s[4], s[5]); v.w = f2h2u(s[6], s[7]);
    return v;
}

#define RED4(p, a, b, c, d) \
    asm volatile("red.global.add.v4.f32 [%0], {%1,%2,%3,%4};" \
                 :: "l"(p), "f"(a), "f"(b), "f"(c), "f"(d) : "memory")
#define REDH8(p, a, b, c, d) \
    asm volatile("red.global.add.noftz.v4.f16x2 [%0], {%1,%2,%3,%4};" \
                 :: "l"(p), "r"(a), "r"(b), "r"(c), "r"(d) : "memory")

__device__ __forceinline__ void lane_flush16(int b, const float* v, float* gbase) {
    float* p = gbase + b * 16;
    RED4(p,      v[0],  v[1],  v[2],  v[3]);
    RED4(p + 4,  v[4],  v[5],  v[6],  v[7]);
    RED4(p + 8,  v[8],  v[9],  v[10], v[11]);
    RED4(p + 12, v[12], v[13], v[14], v[15]);
}

__device__ __forceinline__ void warp_flush16(int curB, float* v, float* gbase) {
    const unsigned full = 0xffffffffu;
    int b0 = __shfl_sync(full, curB, 0);
    bool uni = __all_sync(full, (curB == b0) || (curB < 0));
    if (uni) {
#pragma unroll
        for (int h = 0; h < 16; h++) {
            float s = v[h];
            s += __shfl_xor_sync(full, s, 16);
            s += __shfl_xor_sync(full, s, 8);
            s += __shfl_xor_sync(full, s, 4);
            s += __shfl_xor_sync(full, s, 2);
            s += __shfl_xor_sync(full, s, 1);
            v[h] = s;
        }
        if (((threadIdx.x & 31) == 0) && b0 >= 0) lane_flush16(b0, v, gbase);
    } else if (curB >= 0) {
        lane_flush16(curB, v, gbase);
    }
}

// ---------------- setup kernels ----------------
__global__ void __launch_bounds__(256) setup_node_kernel(
    const float* __restrict__ x,
    const float* __restrict__ Wx_enc, const float* __restrict__ bx_enc,
    const float* __restrict__ We_core, int N) {
    __shared__ __align__(16) float sWS[16][16], sWD[16][16];
    __shared__ float sWenc[16], sBenc[16];
    int t = threadIdx.x, k = t >> 4, h = t & 15;
    sWS[k][h] = We_core[(32 + k) * 16 + h] + We_core[(48 + k) * 16 + h];
    sWD[k][h] = We_core[(64 + k) * 16 + h] + We_core[(80 + k) * 16 + h];
    if (t < 16) { sWenc[t] = Wx_enc[t]; sBenc[t] = bx_enc[t]; }
    __syncthreads();
    int n = blockIdx.x * 256 + t;
    if (n >= N) return;
    float xv = x[n];
    float x1[16];
#pragma unroll
    for (int hh = 0; hh < 16; hh++) x1[hh] = fmaxf(fmaf(xv, sWenc[hh], sBenc[hh]), 0.f);
    float ps[16], pd[16];
#pragma unroll
    for (int hh = 0; hh < 16; hh++) { ps[hh] = 0.f; pd[hh] = 0.f; }
    mac16(sWS, x1, ps);
    mac16(sWD, x1, pd);
    uint4* os = reinterpret_cast<uint4*>(d_projS + (size_t)n * 16);
    uint4* od = reinterpret_cast<uint4*>(d_projD + (size_t)n * 16);
    os[0] = pack8h(ps); os[1] = pack8h(ps + 8);
    od[0] = pack8h(pd); od[1] = pack8h(pd + 8);
}

__global__ void setup_global_kernel(
    const float* __restrict__ g,
    const float* __restrict__ Wg_enc, const float* __restrict__ bg_enc,
    const float* __restrict__ We_core, const float* __restrict__ be_core,
    const float* __restrict__ Wx_core, const float* __restrict__ bx_core, int B) {
    int t = threadIdx.x;
    if (t < B) {
        float g1 = fmaxf(fmaf(g[t], Wg_enc[0], bg_enc[0]), 0.f);
        d_small[G1O + t] = g1;
        d_small[GCO + t] = g1;
    }
    __syncthreads();
    if (t < B * 16) {
        int b = t >> 4, h = t & 15;
        float g1 = d_small[G1O + b];
        d_small[GPE + t] = fmaf(g1, We_core[96 * 16 + h] + We_core[97 * 16 + h], be_core[h]);
        d_small[GPX + t] = fmaf(g1, Wx_core[48 * 16 + h] + Wx_core[49 * 16 + h], bx_core[h]);
    }
}

// ---------------- edge kernel ----------------
template <int STEP>
__global__ void __launch_bounds__(256) edge_kernel(
    const float* __restrict__ e,
    const int* __restrict__ src, const int* __restrict__ dst,
    const int* __restrict__ eidx,
    const float* __restrict__ We_enc, const float* __restrict__ be_enc,
    const float* __restrict__ We_core,
    const float* __restrict__ We_dec, const float* __restrict__ be_dec,
    const float* __restrict__ We_out, const float* __restrict__ be_out,
    float* __restrict__ out_e, int E) {
    __shared__ __align__(16) u64 sWa2[16][8], sWb2[16][8], sWdec2[16][8];
    __shared__ __align__(16) u64 sGproj2[NB][8];
    __shared__ u64 sBdec2[8];
    __shared__ float sWenc[16], sBenc[16], sWoutT[2][16], sBout[2];

    int t = threadIdx.x;
    if (t < 128) {
        int k = t >> 3, j = t & 7;
        if (STEP == 1) {
            sWa2[k][j] = pack2(We_core[k * 16 + 2 * j] + We_core[(16 + k) * 16 + 2 * j],
                               We_core[k * 16 + 2 * j + 1] + We_core[(16 + k) * 16 + 2 * j + 1]);
        } else {
            sWa2[k][j] = pack2(We_core[k * 16 + 2 * j], We_core[k * 16 + 2 * j + 1]);
            sWb2[k][j] = pack2(We_core[(16 + k) * 16 + 2 * j], We_core[(16 + k) * 16 + 2 * j + 1]);
        }
        sWdec2[k][j] = pack2(We_dec[k * 16 + 2 * j], We_dec[k * 16 + 2 * j + 1]);
        sGproj2[k][j] = pack2(d_small[GPE + k * 16 + 2 * j], d_small[GPE + k * 16 + 2 * j + 1]);
    }
    if (t < 16) {
        sWenc[t] = We_enc[t]; sBenc[t] = be_enc[t];
        sWoutT[0][t] = We_out[2 * t]; sWoutT[1][t] = We_out[2 * t + 1];
    }
    if (t < 8) sBdec2[t] = pack2(be_dec[2 * t], be_dec[2 * t + 1]);
    if (t < 2) sBout[t] = be_out[t];
    __syncthreads();

    float eAgg[16];
#pragma unroll
    for (int h = 0; h < 16; h++) eAgg[h] = 0.f;
    int curB = -1;

    int base = blockIdx.x * (256 * EPT);
#pragma unroll
    for (int it = 0; it < EPT; ++it) {
        int i = base + it * 256 + t;
        if (i < E) {
            float ev = e[i];
            int s = src[i], d = dst[i], b = eidx[i];

            const uint4* ps = reinterpret_cast<const uint4*>(d_projS + (size_t)s * 16);
            const uint4* pd = reinterpret_cast<const uint4*>(d_projD + (size_t)d * 16);
            uint4 s0 = ps[0], s1 = ps[1], d0 = pd[0], d1 = pd[1];

            u64 acc2[8];
            acc2[0] = add2(add2(h2f2(s0.x), h2f2(d0.x)), sGproj2[b][0]);
            acc2[1] = add2(add2(h2f2(s0.y), h2f2(d0.y)), sGproj2[b][1]);
            acc2[2] = add2(add2(h2f2(s0.z), h2f2(d0.z)), sGproj2[b][2]);
            acc2[3] = add2(add2(h2f2(s0.w), h2f2(d0.w)), sGproj2[b][3]);
            acc2[4] = add2(add2(h2f2(s1.x), h2f2(d1.x)), sGproj2[b][4]);
            acc2[5] = add2(add2(h2f2(s1.y), h2f2(d1.y)), sGproj2[b][5]);
            acc2[6] = add2(add2(h2f2(s1.z), h2f2(d1.z)), sGproj2[b][6]);
            acc2[7] = add2(add2(h2f2(s1.w), h2f2(d1.w)), sGproj2[b][7]);

            float e1[16];
#pragma unroll
            for (int h = 0; h < 16; h++)
                e1[h] = fmaxf(fmaf(ev, sWenc[h], sBenc[h]), 0.f);
            mac16_2(sWa2, e1, acc2);
            if (STEP == 2) {
                float ec[16];
#pragma unroll
                for (int h2 = 0; h2 < 8; h2++) {
                    float2 f = __half22float2(d_ec[(size_t)h2 * MAXE + i]);
                    ec[2 * h2] = f.x; ec[2 * h2 + 1] = f.y;
                }
                mac16_2(sWb2, ec, acc2);
            }
            float acc[16];
#pragma unroll
            for (int j = 0; j < 8; j++) unpack2(acc2[j], acc[2 * j], acc[2 * j + 1]);
#pragma unroll
            for (int h = 0; h < 16; h++) acc[h] = fmaxf(acc[h], 0.f);  // e_new

            if (STEP == 1) {
#pragma unroll
                for (int h2 = 0; h2 < 8; h2++)
                    d_ec[(size_t)h2 * MAXE + i] = __floats2half2_rn(acc[2 * h2], acc[2 * h2 + 1]);
                asm volatile("red.global.add.f32 [%0], %1;"
                             :: "l"(d_counts + d), "f"(1.0f) : "memory");
            }
            // fp16 packed scatter-sum onto destination node (2 instructions)
            {
                u32 u0 = f2h2u(acc[0], acc[1]),   u1 = f2h2u(acc[2], acc[3]);
                u32 u2 = f2h2u(acc[4], acc[5]),   u3 = f2h2u(acc[6], acc[7]);
                u32 u4 = f2h2u(acc[8], acc[9]),   u5 = f2h2u(acc[10], acc[11]);
                u32 u6 = f2h2u(acc[12], acc[13]), u7 = f2h2u(acc[14], acc[15]);
                __half2* p = d_aggE2 + (size_t)d * 8;
                REDH8(p, u0, u1, u2, u3);
                REDH8(p + 4, u4, u5, u6, u7);
            }
            // per-graph edge aggregation
            if (b != curB) {
                if (curB >= 0) lane_flush16(curB, eAgg, d_small + EAGG);
                curB = b;
#pragma unroll
                for (int h = 0; h < 16; h++) eAgg[h] = 0.f;
            }
#pragma unroll
            for (int h = 0; h < 16; h++) eAgg[h] += acc[h];

            // decoder + output head
            u64 ed2[8];
#pragma unroll
            for (int j = 0; j < 8; j++) ed2[j] = sBdec2[j];
            mac16_2(sWdec2, acc, ed2);
            float ed[16];
#pragma unroll
            for (int j = 0; j < 8; j++) unpack2(ed2[j], ed[2 * j], ed[2 * j + 1]);
            float o0 = sBout[0], o1 = sBout[1];
#pragma unroll
            for (int k = 0; k < 16; k++) {
                float r = fmaxf(ed[k], 0.f);
                o0 = fmaf(r, sWoutT[0][k], o0);
                o1 = fmaf(r, sWoutT[1][k], o1);
            }
            reinterpret_cast<float2*>(out_e)[(size_t)(STEP - 1) * E + i] = make_float2(o0, o1);
        }
    }
    warp_flush16(curB, eAgg, d_small + EAGG);
}

// ---------------- node kernel ----------------
template <int STEP>
__global__ void __launch_bounds__(256) node_kernel(
    const float* __restrict__ x, const int* __restrict__ nidx,
    const float* __restrict__ Wx_enc, const float* __restrict__ bx_enc,
    const float* __restrict__ Wx_core, const float* __restrict__ We_core,
    const float* __restrict__ Wx_dec, const float* __restrict__ bx_dec,
    const float* __restrict__ Wx_out, const float* __restrict__ bx_out,
    float* __restrict__ out_x, int N) {
    __shared__ __align__(16) u64 sWxA2[16][8], sWxB2[16][8], sWagg2[16][8], sWdec2[16][8];
    __shared__ __align__(16) u64 sWSt2[16][8], sWSb2[16][8], sWDt2[16][8], sWDb2[16][8];
    __shared__ __align__(16) u64 sGprojX2[NB][8];
    __shared__ u64 sBdec2[8];
    __shared__ float sWenc[16], sBenc[16], sWoutT[2][16], sBout[2];

    int t = threadIdx.x;
    if (t < 128) {
        int k = t >> 3, j = t & 7;
        int c0 = 2 * j, c1 = 2 * j + 1;
        if (STEP == 1) {
            sWxA2[k][j] = pack2(Wx_core[k * 16 + c0] + Wx_core[(16 + k) * 16 + c0],
                                Wx_core[k * 16 + c1] + Wx_core[(16 + k) * 16 + c1]);
            sWSt2[k][j] = pack2(We_core[(32 + k) * 16 + c0], We_core[(32 + k) * 16 + c1]);
            sWSb2[k][j] = pack2(We_core[(48 + k) * 16 + c0], We_core[(48 + k) * 16 + c1]);
            sWDt2[k][j] = pack2(We_core[(64 + k) * 16 + c0], We_core[(64 + k) * 16 + c1]);
            sWDb2[k][j] = pack2(We_core[(80 + k) * 16 + c0], We_core[(80 + k) * 16 + c1]);
        } else {
            sWxA2[k][j] = pack2(Wx_core[k * 16 + c0], Wx_core[k * 16 + c1]);
            sWxB2[k][j] = pack2(Wx_core[(16 + k) * 16 + c0], Wx_core[(16 + k) * 16 + c1]);
        }
        sWagg2[k][j] = pack2(Wx_core[(32 + k) * 16 + c0], Wx_core[(32 + k) * 16 + c1]);
        sWdec2[k][j] = pack2(Wx_dec[k * 16 + c0], Wx_dec[k * 16 + c1]);
        sGprojX2[k][j] = pack2(d_small[GPX + k * 16 + c0], d_small[GPX + k * 16 + c1]);
    }
    if (t < 16) {
        sWenc[t] = Wx_enc[t]; sBenc[t] = bx_enc[t];
        sWoutT[0][t] = Wx_out[2 * t]; sWoutT[1][t] = Wx_out[2 * t + 1];
    }
    if (t < 8) sBdec2[t] = pack2(bx_dec[2 * t], bx_dec[2 * t + 1]);
    if (t < 2) sBout[t] = bx_out[t];
    __syncthreads();

    int n = blockIdx.x * 256 + t;
    float xnew[16];
#pragma unroll
    for (int hh = 0; hh < 16; hh++) xnew[hh] = 0.f;
    int b = -1;

    if (n < N) {
        b = nidx[n];
        float xv = x[n];
        float x1[16];
#pragma unroll
        for (int hh = 0; hh < 16; hh++) x1[hh] = fmaxf(fmaf(xv, sWenc[hh], sBenc[hh]), 0.f);
        u64 acc2[8];
#pragma unroll
        for (int j = 0; j < 8; j++) acc2[j] = sGprojX2[b][j];
        mac16_2(sWxA2, x1, acc2);
        float xc[16];
        if (STEP == 2) {
            const float4* pc = reinterpret_cast<const float4*>(d_xc + (size_t)n * 16);
#pragma unroll
            for (int q = 0; q < 4; q++) {
                float4 v = pc[q];
                xc[4 * q] = v.x; xc[4 * q + 1] = v.y; xc[4 * q + 2] = v.z; xc[4 * q + 3] = v.w;
            }
            mac16_2(sWxB2, xc, acc2);
        }
        float inv = 1.0f / fmaxf(d_counts[n], 1.0f);
        float am[16];
        {
            const uint4* pa = reinterpret_cast<const uint4*>(d_aggE2 + (size_t)n * 8);
            uint4 a0 = pa[0], a1 = pa[1];
            u32 w[8] = {a0.x, a0.y, a0.z, a0.w, a1.x, a1.y, a1.z, a1.w};
#pragma unroll
            for (int q = 0; q < 8; q++) {
                float2 f = __half22float2(*reinterpret_cast<__half2*>(&w[q]));
                am[2 * q] = f.x * inv; am[2 * q + 1] = f.y * inv;
            }
        }
        mac16_2(sWagg2, am, acc2);
#pragma unroll
        for (int j = 0; j < 8; j++) unpack2(acc2[j], xnew[2 * j], xnew[2 * j + 1]);
#pragma unroll
        for (int hh = 0; hh < 16; hh++) xnew[hh] = fmaxf(xnew[hh], 0.f);

        if (STEP == 1) {
            float4* pc = reinterpret_cast<float4*>(d_xc + (size_t)n * 16);
#pragma unroll
            for (int q = 0; q < 4; q++)
                pc[q] = make_float4(xnew[4 * q], xnew[4 * q + 1], xnew[4 * q + 2], xnew[4 * q + 3]);
            u64 psv2[8], pdv2[8];
#pragma unroll
            for (int j = 0; j < 8; j++) { psv2[j] = 0ull; pdv2[j] = 0ull; }
            mac16_2(sWSt2, x1, psv2);  mac16_2(sWSb2, xnew, psv2);
            mac16_2(sWDt2, x1, pdv2);  mac16_2(sWDb2, xnew, pdv2);
            float psv[16], pdv[16];
#pragma unroll
            for (int j = 0; j < 8; j++) {
                unpack2(psv2[j], psv[2 * j], psv[2 * j + 1]);
                unpack2(pdv2[j], pdv[2 * j], pdv[2 * j + 1]);
            }
            uint4* os = reinterpret_cast<uint4*>(d_projS + (size_t)n * 16);
            uint4* od = reinterpret_cast<uint4*>(d_projD + (size_t)n * 16);
            os[0] = pack8h(psv); os[1] = pack8h(psv + 8);
            od[0] = pack8h(pdv); od[1] = pack8h(pdv + 8);
        }
        u64 xd2[8];
#pragma unroll
        for (int j = 0; j < 8; j++) xd2[j] = sBdec2[j];
        mac16_2(sWdec2, xnew, xd2);
        float xd[16];
#pragma unroll
        for (int j = 0; j < 8; j++) unpack2(xd2[j], xd[2 * j], xd[2 * j + 1]);
        float o0 = sBout[0], o1 = sBout[1];
#pragma unroll
        for (int kk = 0; kk < 16; kk++) {
            float r = fmaxf(xd[kk], 0.f);
            o0 = fmaf(r, sWoutT[0][kk], o0);
            o1 = fmaf(r, sWoutT[1][kk], o1);
        }
        reinterpret_cast<float2*>(out_x)[(size_t)(STEP - 1) * N + n] = make_float2(o0, o1);
    }
    warp_flush16(b, xnew, d_small + NAGG);
}

// ---------------- global kernel ----------------
template <int STEP>
__global__ void global_kernel(
    const float* __restrict__ Wg_core, const float* __restrict__ bg_core,
    const float* __restrict__ Wg_dec, const float* __restrict__ bg_dec,
    const float* __restrict__ Wg_out, const float* __restrict__ bg_out,
    const float* __restrict__ We_core, const float* __restrict__ be_core,
    const float* __restrict__ Wx_core, const float* __restrict__ bx_core,
    float* __restrict__ out_g, int B) {
    int t = threadIdx.x;
    if (t < B) {
        float g1 = d_small[G1O + t], gc = d_small[GCO + t];
        float acc = bg_core[0] + g1 * Wg_core[0] + gc * Wg_core[1];
#pragma unroll
        for (int h = 0; h < 16; h++) acc = fmaf(d_small[NAGG + t * 16 + h], Wg_core[2 + h], acc);
#pragma unroll
        for (int h = 0; h < 16; h++) acc = fmaf(d_small[EAGG + t * 16 + h], Wg_core[18 + h], acc);
        float gn = fmaxf(acc, 0.f);
        d_small[GCO + t] = gn;
        float gd = fmaxf(fmaf(gn, Wg_dec[0], bg_dec[0]), 0.f);
        out_g[(STEP - 1) * B + t] = fmaf(gd, Wg_out[0], bg_out[0]);
    }
    __syncthreads();
    if (STEP == 1 && t < B * 16) {
        int b = t >> 4, h = t & 15;
        float g1 = d_small[G1O + b], gn = d_small[GCO + b];
        d_small[GPE + t] = fmaf(g1, We_core[96 * 16 + h], fmaf(gn, We_core[97 * 16 + h], be_core[h]));
        d_small[GPX + t] = fmaf(g1, Wx_core[48 * 16 + h], fmaf(gn, Wx_core[49 * 16 + h], bx_core[h]));
    }
}

// ---------------- launch ----------------
extern "C" void kernel_launch(void* const* d_in, const int* in_sizes, int n_in,
                              void* d_out, int out_size) {
    const float* x       = (const float*)d_in[0];
    const float* e       = (const float*)d_in[1];
    const float* g       = (const float*)d_in[2];
    const float* We_enc  = (const float*)d_in[3];
    const float* be_enc  = (const float*)d_in[4];
    const float* Wx_enc  = (const float*)d_in[5];
    const float* bx_enc  = (const float*)d_in[6];
    const float* Wg_enc  = (const float*)d_in[7];
    const float* bg_enc  = (const float*)d_in[8];
    const float* We_core = (const float*)d_in[9];
    const float* be_core = (const float*)d_in[10];
    const float* Wx_core = (const float*)d_in[11];
    const float* bx_core = (const float*)d_in[12];
    const float* Wg_core = (const float*)d_in[13];
    const float* bg_core = (const float*)d_in[14];
    const float* We_dec  = (const float*)d_in[15];
    const float* be_dec  = (const float*)d_in[16];
    const float* Wx_dec  = (const float*)d_in[17];
    const float* bx_dec  = (const float*)d_in[18];
    const float* Wg_dec  = (const float*)d_in[19];
    const float* bg_dec  = (const float*)d_in[20];
    const float* We_out  = (const float*)d_in[21];
    const float* be_out  = (const float*)d_in[22];
    const float* Wx_out  = (const float*)d_in[23];
    const float* bx_out  = (const float*)d_in[24];
    const float* Wg_out  = (const float*)d_in[25];
    const float* bg_out  = (const float*)d_in[26];
    const int*   edges   = (const int*)d_in[27];
    const int*   nidx    = (const int*)d_in[28];
    const int*   eidx    = (const int*)d_in[29];

    int N = in_sizes[0];
    int E = in_sizes[1];
    int B = in_sizes[2];
    float* out = (float*)d_out;
    float* out_e = out;
    float* out_x = out + (size_t)4 * E;
    float* out_g = out + (size_t)4 * E + (size_t)4 * N;

    const int* src = edges;
    const int* dst = edges + E;

    void *pCounts, *pAggE, *pSmall;
    cudaGetSymbolAddress(&pCounts, d_counts);
    cudaGetSymbolAddress(&pAggE, d_aggE2);
    cudaGetSymbolAddress(&pSmall, d_small);

    cudaMemsetAsync(pCounts, 0, (size_t)N * sizeof(float), 0);
    cudaMemsetAsync(pAggE, 0, (size_t)N * 8 * sizeof(__half2), 0);
    cudaMemsetAsync((char*)pSmall + NAGG * sizeof(float), 0, 512 * sizeof(float), 0);

    setup_node_kernel<<<(N + 255) / 256, 256>>>(x, Wx_enc, bx_enc, We_core, N);
    setup_global_kernel<<<1, 256>>>(g, Wg_enc, bg_enc, We_core, be_core, Wx_core, bx_core, B);

    int egrid = (E + 256 * EPT - 1) / (256 * EPT);
    int ngrid = (N + 255) / 256;

    // ---- step 1 ----
    edge_kernel<1><<<egrid, 256>>>(e, src, dst, eidx, We_enc, be_enc, We_core,
                                   We_dec, be_dec, We_out, be_out, out_e, E);
    node_kernel<1><<<ngrid, 256>>>(x, nidx, Wx_enc, bx_enc, Wx_core, We_core,
                                   Wx_dec, bx_dec, Wx_out, bx_out, out_x, N);
    global_kernel<1><<<1, 256>>>(Wg_core, bg_core, Wg_dec, bg_dec, Wg_out, bg_out,
                                 We_core, be_core, Wx_core, bx_core, out_g, B);

    cudaMemsetAsync(pAggE, 0, (size_t)N * 8 * sizeof(__half2), 0);
    cudaMemsetAsync((char*)pSmall + NAGG * sizeof(float), 0, 512 * sizeof(float), 0);

    // ---- step 2 ----
    edge_kernel<2><<<egrid, 256>>>(e, src, dst, eidx, We_enc, be_enc, We_core,
                                   We_dec, be_dec, We_out, be_out, out_e, E);
    node_kernel<2><<<ngrid, 256>>>(x, nidx, Wx_enc, bx_enc, Wx_core, We_core,
                                   Wx_dec, bx_dec, Wx_out, bx_out, out_x, N);
    global_kernel<2><<<1, 256>>>(Wg_core, bg_core, Wg_dec, bg_dec, Wg_out, bg_out,
                                 We_core, be_core, Wx_core, bx_core, out_g, B);
}